// round 8
// baseline (speedup 1.0000x reference)
#include <cuda_runtime.h>
#include <cuda_bf16.h>
#include <cstdint>
#include <math.h>

#define NU 200000
#define NP 100000
#define NN 300000
#define NE 1000000
#define CAP 64             // adjacency slots per node (Poisson(~6.7): overflow impossible)
#define STRIDE 72          // bf16 units, padded row stride for smem tiles
#define GU 1563            // ceil(NU/128)
#define GP 782             // ceil(NP/128)

// Scratch (module-static device memory; sanctioned by harness rules)
__device__ __nv_bfloat162 g_hA[(size_t)NN * 32];   // messages ping
__device__ __nv_bfloat162 g_hB[(size_t)NN * 32];   // messages pong
__device__ int            g_cnt[NN];
__device__ int            g_adj[(size_t)NN * CAP];
__device__ float          g_dis[NN];

// ---------------------------------------------------------------------------
// helpers
// ---------------------------------------------------------------------------
__device__ __forceinline__ unsigned pack_bf2(float x, float y) {
    __nv_bfloat162 h = __floats2bfloat162_rn(x, y);
    return *(unsigned*)&h;
}

__device__ __forceinline__ void ldmA(uint32_t addr, uint32_t& a0, uint32_t& a1,
                                     uint32_t& a2, uint32_t& a3) {
    asm volatile("ldmatrix.sync.aligned.m8n8.x4.shared.b16 {%0,%1,%2,%3},[%4];"
                 : "=r"(a0), "=r"(a1), "=r"(a2), "=r"(a3) : "r"(addr));
}
__device__ __forceinline__ void ldmBT(uint32_t addr, uint32_t& b0, uint32_t& b1,
                                      uint32_t& b2, uint32_t& b3) {
    asm volatile("ldmatrix.sync.aligned.m8n8.x4.trans.shared.b16 {%0,%1,%2,%3},[%4];"
                 : "=r"(b0), "=r"(b1), "=r"(b2), "=r"(b3) : "r"(addr));
}
__device__ __forceinline__ void mma16816(float* c, uint32_t a0, uint32_t a1,
                                         uint32_t a2, uint32_t a3,
                                         uint32_t b0, uint32_t b1) {
    asm volatile("mma.sync.aligned.m16n8k16.row.col.f32.bf16.bf16.f32 "
                 "{%0,%1,%2,%3},{%4,%5,%6,%7},{%8,%9},{%0,%1,%2,%3};"
                 : "+f"(c[0]), "+f"(c[1]), "+f"(c[2]), "+f"(c[3])
                 : "r"(a0), "r"(a1), "r"(a2), "r"(a3), "r"(b0), "r"(b1));
}

// One K=64 chunk: C[warp 16 rows x 64 cols] += xt_warp[16x64] @ wt[64x64]
__device__ __forceinline__ void mma_core(uint32_t xtw, uint32_t wtb, int l,
                                         float cf[8][4]) {
    uint32_t rowOff = (uint32_t)(((l & 7) + ((l >> 3) & 1) * 8) * STRIDE + (l >> 4) * 8) * 2;
    uint32_t aAddr = xtw + rowOff;
    uint32_t bAddr = wtb + rowOff;
    #pragma unroll
    for (int ks = 0; ks < 4; ks++) {
        uint32_t a0, a1, a2, a3;
        ldmA(aAddr + ks * 32, a0, a1, a2, a3);
        #pragma unroll
        for (int np = 0; np < 4; np++) {
            uint32_t b0, b1, b2, b3;
            ldmBT(bAddr + (uint32_t)(ks * 16 * STRIDE + np * 16) * 2, b0, b1, b2, b3);
            mma16816(cf[2 * np],     a0, a1, a2, a3, b0, b1);
            mma16816(cf[2 * np + 1], a0, a1, a2, a3, b2, b3);
        }
    }
}

// ---------------------------------------------------------------------------
// Adjacency build + normalization
// ---------------------------------------------------------------------------
__global__ void k_zero() {
    int n = blockIdx.x * blockDim.x + threadIdx.x;
    if (n < NN) g_cnt[n] = 0;
}
__global__ void k_build(const int* __restrict__ ei) {
    int e = blockIdx.x * blockDim.x + threadIdx.x;
    if (e < NE) {
        int u = ei[e];
        int p = ei[NE + e];
        int s1 = atomicAdd(&g_cnt[u], 1);
        if (s1 < CAP) g_adj[(size_t)u * CAP + s1] = p;   // message p -> u
        int s2 = atomicAdd(&g_cnt[p], 1);
        if (s2 < CAP) g_adj[(size_t)p * CAP + s2] = u;   // message u -> p
    }
}
__global__ void k_dis() {
    int n = blockIdx.x * blockDim.x + threadIdx.x;
    if (n < NN) g_dis[n] = rsqrtf((float)(g_cnt[n] + 1));   // +1 self loop
}

// ---------------------------------------------------------------------------
// K1: feat + conv1 fused.
//   X = feat(128) @ Wf + bf + emb     (stage A, kept in smem bf16)
//   hs1 = (X @ c1W) * dis             (stage B) -> g_hA
// Split grid: blocks [0,GU) users, [GU,GU+GP) products.
// ---------------------------------------------------------------------------
__global__ __launch_bounds__(256) void k_feat_conv1(
    const float* __restrict__ uf, const float* __restrict__ pf,
    const float* __restrict__ ue, const float* __restrict__ pe,
    const float* __restrict__ Wuf, const float* __restrict__ buf_,
    const float* __restrict__ Wpf, const float* __restrict__ bpf,
    const float* __restrict__ c1W)
{
    __shared__ __align__(16) __nv_bfloat16 xt[128 * STRIDE];
    __shared__ __align__(16) __nv_bfloat16 wt[64 * STRIDE];
    __shared__ float bs[64];

    int bid = blockIdx.x;
    bool isUser = bid < GU;
    int lrow0 = isUser ? bid * 128 : (bid - GU) * 128;
    int nloc  = isUser ? NU : NP;
    const float* feat = isUser ? uf : pf;
    const float* emb  = isUser ? ue : pe;
    const float* W    = isUser ? Wuf : Wpf;
    const float* b    = isUser ? buf_ : bpf;
    int grow0 = isUser ? lrow0 : NU + lrow0;

    int tid = threadIdx.x;
    if (tid < 32) ((float2*)bs)[tid] = ((const float2*)b)[tid];

    int l = tid & 31, w = tid >> 5;
    float cf[8][4];
    #pragma unroll
    for (int j = 0; j < 8; j++)
        #pragma unroll
        for (int q = 0; q < 4; q++) cf[j][q] = 0.f;

    const float4* W4 = (const float4*)W;
    const float4* f4 = (const float4*)feat;   // row stride 32 float4

    // ---- stage A: X = feat @ Wf (K=128 in 2 chunks) ----
    #pragma unroll
    for (int ch = 0; ch < 2; ch++) {
        if (ch) __syncthreads();
        #pragma unroll
        for (int i = 0; i < 4; i++) {
            int idx = tid + i * 256, r = idx >> 4, c4 = idx & 15;
            float4 v = W4[ch * 1024 + idx];
            *(uint2*)(&wt[r * STRIDE + c4 * 4]) =
                make_uint2(pack_bf2(v.x, v.y), pack_bf2(v.z, v.w));
        }
        #pragma unroll
        for (int i = 0; i < 8; i++) {
            int idx = tid + i * 256, r = idx >> 4, c4 = idx & 15;
            int lr = lrow0 + r;
            float4 v = make_float4(0.f, 0.f, 0.f, 0.f);
            if (lr < nloc) v = f4[(size_t)lr * 32 + ch * 16 + c4];
            *(uint2*)(&xt[r * STRIDE + c4 * 4]) =
                make_uint2(pack_bf2(v.x, v.y), pack_bf2(v.z, v.w));
        }
        __syncthreads();
        mma_core((uint32_t)__cvta_generic_to_shared(xt) + (uint32_t)(w * 16 * STRIDE) * 2,
                 (uint32_t)__cvta_generic_to_shared(wt), l, cf);
    }

    // ---- epilogue A: X + bf + emb -> xt (own warp slice; warp-safe) ----
    int rl = w * 16 + (l >> 2);
    #pragma unroll
    for (int half = 0; half < 2; half++) {
        int rloc = rl + half * 8;
        int lr = lrow0 + rloc;
        #pragma unroll
        for (int j = 0; j < 8; j++) {
            int c2 = j * 4 + (l & 3);
            unsigned v = 0u;
            if (lr < nloc) {
                float2 ev = ((const float2*)emb)[(size_t)lr * 32 + c2];
                v = pack_bf2(cf[j][half * 2 + 0] + bs[c2 * 2]     + ev.x,
                             cf[j][half * 2 + 1] + bs[c2 * 2 + 1] + ev.y);
            }
            *(unsigned*)(&xt[rloc * STRIDE + c2 * 2]) = v;
        }
    }
    #pragma unroll
    for (int j = 0; j < 8; j++)
        #pragma unroll
        for (int q = 0; q < 4; q++) cf[j][q] = 0.f;
    __syncthreads();

    // ---- stage B: hs1 = (X @ c1W) * dis ----
    #pragma unroll
    for (int i = 0; i < 4; i++) {
        int idx = tid + i * 256, r = idx >> 4, c4 = idx & 15;
        float4 v = ((const float4*)c1W)[idx];
        *(uint2*)(&wt[r * STRIDE + c4 * 4]) =
            make_uint2(pack_bf2(v.x, v.y), pack_bf2(v.z, v.w));
    }
    __syncthreads();
    mma_core((uint32_t)__cvta_generic_to_shared(xt) + (uint32_t)(w * 16 * STRIDE) * 2,
             (uint32_t)__cvta_generic_to_shared(wt), l, cf);

    #pragma unroll
    for (int half = 0; half < 2; half++) {
        int lr = lrow0 + rl + half * 8;
        if (lr < nloc) {
            int gr = grow0 + rl + half * 8;
            float d = g_dis[gr];
            #pragma unroll
            for (int j = 0; j < 8; j++) {
                int c2 = j * 4 + (l & 3);
                g_hA[(size_t)gr * 32 + c2] = __floats2bfloat162_rn(
                    cf[j][half * 2 + 0] * d, cf[j][half * 2 + 1] * d);
            }
        }
    }
}

// ---------------------------------------------------------------------------
// K2/K3: agg + matmul fused.
//   xin[n] = act( bIn + dis[n]*(hin[n] + sum_{src} hin[src]) )
//   hout[n] = (xin @ W) * (epiDis ? dis[n] : 1)
// Split grid; Wu/Wp allow per-half weights (prednode).
// ---------------------------------------------------------------------------
__global__ __launch_bounds__(256) void k_aggmm(
    int bufSel,                         // 0: in g_hA out g_hB; 1: in g_hB out g_hA
    const float* __restrict__ Wu, const float* __restrict__ Wp,
    const float* __restrict__ bIn, int doRelu, int epiDis)
{
    __shared__ __align__(16) __nv_bfloat16 xt[128 * STRIDE];
    __shared__ __align__(16) __nv_bfloat16 wt[64 * STRIDE];
    __shared__ float bs[64];

    const unsigned* hin = bufSel ? (const unsigned*)g_hB : (const unsigned*)g_hA;
    __nv_bfloat162* hout = bufSel ? g_hA : g_hB;

    int bid = blockIdx.x;
    bool isUser = bid < GU;
    int lrow0 = isUser ? bid * 128 : (bid - GU) * 128;
    int nloc  = isUser ? NU : NP;
    int grow0 = isUser ? lrow0 : NU + lrow0;
    const float* W = isUser ? Wu : Wp;

    int tid = threadIdx.x;
    int l = tid & 31, w = tid >> 5;
    if (tid < 32) ((float2*)bs)[tid] = ((const float2*)bIn)[tid];

    #pragma unroll
    for (int i = 0; i < 4; i++) {
        int idx = tid + i * 256, r = idx >> 4, c4 = idx & 15;
        float4 v = ((const float4*)W)[idx];
        *(uint2*)(&wt[r * STRIDE + c4 * 4]) =
            make_uint2(pack_bf2(v.x, v.y), pack_bf2(v.z, v.w));
    }
    __syncthreads();   // bs visible to agg phase

    // ---- agg phase: warp w handles 16 nodes ----
    unsigned* xrow = (unsigned*)xt;
    for (int nl = 0; nl < 16; nl++) {
        int rloc = w * 16 + nl;
        int lr = lrow0 + rloc;
        unsigned v = 0u;
        if (lr < nloc) {
            int n = grow0 + rloc;
            unsigned own = hin[(size_t)n * 32 + l];
            float2 fo = __bfloat1622float2(*(__nv_bfloat162*)&own);
            float sx = fo.x, sy = fo.y;
            int c = g_cnt[n];
            if (c > CAP) c = CAP;
            size_t base = (size_t)n * CAP;
            for (int i0 = 0; i0 < c; i0 += 32) {
                int m = min(32, c - i0);
                int srcl = (l < m) ? g_adj[base + i0 + l] : 0;
                int i = 0;
                for (; i + 1 < m; i += 2) {
                    int s0 = __shfl_sync(0xffffffffu, srcl, i);
                    int s1 = __shfl_sync(0xffffffffu, srcl, i + 1);
                    unsigned r0 = hin[(size_t)s0 * 32 + l];
                    unsigned r1 = hin[(size_t)s1 * 32 + l];
                    float2 f0 = __bfloat1622float2(*(__nv_bfloat162*)&r0);
                    float2 f1 = __bfloat1622float2(*(__nv_bfloat162*)&r1);
                    sx += f0.x + f1.x;
                    sy += f0.y + f1.y;
                }
                if (i < m) {
                    int s0 = __shfl_sync(0xffffffffu, srcl, i);
                    unsigned r0 = hin[(size_t)s0 * 32 + l];
                    float2 f0 = __bfloat1622float2(*(__nv_bfloat162*)&r0);
                    sx += f0.x;
                    sy += f0.y;
                }
            }
            float d = g_dis[n];
            float vx = bs[2 * l]     + d * sx;
            float vy = bs[2 * l + 1] + d * sy;
            if (doRelu) { vx = fmaxf(vx, 0.f); vy = fmaxf(vy, 0.f); }
            v = pack_bf2(vx, vy);
        }
        xrow[rloc * (STRIDE / 2) + l] = v;
    }
    __syncthreads();

    // ---- matmul phase ----
    float cf[8][4];
    #pragma unroll
    for (int j = 0; j < 8; j++)
        #pragma unroll
        for (int q = 0; q < 4; q++) cf[j][q] = 0.f;

    mma_core((uint32_t)__cvta_generic_to_shared(xt) + (uint32_t)(w * 16 * STRIDE) * 2,
             (uint32_t)__cvta_generic_to_shared(wt), l, cf);

    int rl = w * 16 + (l >> 2);
    #pragma unroll
    for (int half = 0; half < 2; half++) {
        int lr = lrow0 + rl + half * 8;
        if (lr < nloc) {
            int gr = grow0 + rl + half * 8;
            float d = epiDis ? g_dis[gr] : 1.f;
            #pragma unroll
            for (int j = 0; j < 8; j++) {
                int c2 = j * 4 + (l & 3);
                hout[(size_t)gr * 32 + c2] = __floats2bfloat162_rn(
                    cf[j][half * 2 + 0] * d, cf[j][half * 2 + 1] * d);
            }
        }
    }
}

// ---------------------------------------------------------------------------
// K4: edge predictor. h = relu(A[u]+B[p]+b1); out = 5*sigmoid(h.W2 + b2)
// 16 lanes per edge (2 edges/warp); coalesced uint2 row reads from g_hA.
// ---------------------------------------------------------------------------
__global__ __launch_bounds__(256) void k_prededge(
    const int* __restrict__ ei,
    const float* __restrict__ b1, const float* __restrict__ W2,
    const float* __restrict__ b2, float* __restrict__ out)
{
    __shared__ float b1s[64], w2s[64];
    __shared__ float b2v;
    int tid = threadIdx.x;
    if (tid < 64) { b1s[tid] = b1[tid]; w2s[tid] = W2[tid]; }
    if (tid == 0) b2v = b2[0];
    __syncthreads();

    int e = blockIdx.x * 16 + (tid >> 4);
    if (e >= NE) return;
    int lg = tid & 15;
    int u = ei[e];
    int p = ei[NE + e];
    uint2 ar = ((const uint2*)g_hA)[(size_t)u * 16 + lg];
    uint2 br = ((const uint2*)g_hA)[(size_t)(NU + p) * 16 + lg];
    float2 a0 = __bfloat1622float2(*(__nv_bfloat162*)&ar.x);
    float2 a1 = __bfloat1622float2(*(__nv_bfloat162*)&ar.y);
    float2 c0 = __bfloat1622float2(*(__nv_bfloat162*)&br.x);
    float2 c1 = __bfloat1622float2(*(__nv_bfloat162*)&br.y);
    float4 b1v = ((const float4*)b1s)[lg];
    float4 w2v = ((const float4*)w2s)[lg];
    float h0 = fmaxf(a0.x + c0.x + b1v.x, 0.f);
    float h1 = fmaxf(a0.y + c0.y + b1v.y, 0.f);
    float h2 = fmaxf(a1.x + c1.x + b1v.z, 0.f);
    float h3 = fmaxf(a1.y + c1.y + b1v.w, 0.f);
    float part = h0 * w2v.x + h1 * w2v.y + h2 * w2v.z + h3 * w2v.w;
    #pragma unroll
    for (int off = 8; off; off >>= 1)
        part += __shfl_xor_sync(0xffffffffu, part, off);
    if (lg == 0) {
        float z = part + b2v;
        out[e] = 5.f / (1.f + expf(-z));
    }
}

// ---------------------------------------------------------------------------
extern "C" void kernel_launch(void* const* d_in, const int* in_sizes, int n_in,
                              void* d_out, int out_size)
{
    const int*   ei  = (const int*)d_in[0];   // [2, NE] int32
    const float* uf  = (const float*)d_in[1];
    const float* pf  = (const float*)d_in[2];
    const float* ue  = (const float*)d_in[3];
    const float* pe  = (const float*)d_in[4];
    const float* Wuf = (const float*)d_in[5];
    const float* buf_= (const float*)d_in[6];
    const float* Wpf = (const float*)d_in[7];
    const float* bpf = (const float*)d_in[8];
    const float* c1W = (const float*)d_in[9];
    const float* c1b = (const float*)d_in[10];
    const float* c2W = (const float*)d_in[11];
    const float* c2b = (const float*)d_in[12];
    const float* pW1 = (const float*)d_in[13];
    const float* pb1 = (const float*)d_in[14];
    const float* pW2 = (const float*)d_in[15];
    const float* pb2 = (const float*)d_in[16];
    float* out = (float*)d_out;

    k_zero <<<(NN + 255) / 256, 256>>>();
    k_build<<<(NE + 255) / 256, 256>>>(ei);
    k_dis  <<<(NN + 255) / 256, 256>>>();

    // K1: feat + conv1 -> g_hA (hs1)
    k_feat_conv1<<<GU + GP, 256>>>(uf, pf, ue, pe, Wuf, buf_, Wpf, bpf, c1W);

    // K2: agg(hs1) + conv2 -> g_hB (hs2);  xin = relu(c1b + d*(own+sum))
    k_aggmm<<<GU + GP, 256>>>(0, c2W, c2W, c1b, 1, 1);

    // K3: agg(hs2) + prednode -> g_hA (projections);  xin = c2b + d*(own+sum)
    k_aggmm<<<GU + GP, 256>>>(1, pW1, pW1 + 4096, c2b, 0, 0);

    // K4: per-edge combine
    k_prededge<<<NE / 16, 256>>>(ei, pb1, pW2, pb2, out);
}

// round 9
// speedup vs baseline: 1.2269x; 1.2269x over previous
#include <cuda_runtime.h>
#include <cuda_bf16.h>
#include <cstdint>
#include <math.h>

#define NU 200000
#define NP 100000
#define NN 300000
#define NE 1000000
#define CAP 64             // adjacency slots per node (Poisson(~6.7): overflow impossible)
#define STRIDE 72          // bf16 units, padded row stride for smem tiles
#define GU 1563            // ceil(NU/128)
#define GP 782             // ceil(NP/128)

// Scratch (module-static device memory; sanctioned by harness rules)
__device__ __nv_bfloat162 g_xb[(size_t)NN * 32];   // GEMM inputs (x / activated conv out)
__device__ __nv_bfloat162 g_h [(size_t)NN * 32];   // messages / pred projections
__device__ int            g_cnt[NN];
__device__ int            g_adj[(size_t)NN * CAP];

// ---------------------------------------------------------------------------
// helpers
// ---------------------------------------------------------------------------
__device__ __forceinline__ unsigned pack_bf2(float x, float y) {
    __nv_bfloat162 h = __floats2bfloat162_rn(x, y);
    return *(unsigned*)&h;
}
__device__ __forceinline__ float node_dis(int n) {
    return rsqrtf((float)(g_cnt[n] + 1));   // +1 self loop
}

__device__ __forceinline__ void ldmA(uint32_t addr, uint32_t& a0, uint32_t& a1,
                                     uint32_t& a2, uint32_t& a3) {
    asm volatile("ldmatrix.sync.aligned.m8n8.x4.shared.b16 {%0,%1,%2,%3},[%4];"
                 : "=r"(a0), "=r"(a1), "=r"(a2), "=r"(a3) : "r"(addr));
}
__device__ __forceinline__ void ldmBT(uint32_t addr, uint32_t& b0, uint32_t& b1,
                                      uint32_t& b2, uint32_t& b3) {
    asm volatile("ldmatrix.sync.aligned.m8n8.x4.trans.shared.b16 {%0,%1,%2,%3},[%4];"
                 : "=r"(b0), "=r"(b1), "=r"(b2), "=r"(b3) : "r"(addr));
}
__device__ __forceinline__ void mma16816(float* c, uint32_t a0, uint32_t a1,
                                         uint32_t a2, uint32_t a3,
                                         uint32_t b0, uint32_t b1) {
    asm volatile("mma.sync.aligned.m16n8k16.row.col.f32.bf16.bf16.f32 "
                 "{%0,%1,%2,%3},{%4,%5,%6,%7},{%8,%9},{%0,%1,%2,%3};"
                 : "+f"(c[0]), "+f"(c[1]), "+f"(c[2]), "+f"(c[3])
                 : "r"(a0), "r"(a1), "r"(a2), "r"(a3), "r"(b0), "r"(b1));
}

// One K=64 chunk: C[warp 16 rows x 64 cols] += xt_warp[16x64] @ wt[64x64]
__device__ __forceinline__ void mma_core(uint32_t xtw, uint32_t wtb, int l,
                                         float cf[8][4]) {
    uint32_t rowOff = (uint32_t)(((l & 7) + ((l >> 3) & 1) * 8) * STRIDE + (l >> 4) * 8) * 2;
    uint32_t aAddr = xtw + rowOff;
    uint32_t bAddr = wtb + rowOff;
    #pragma unroll
    for (int ks = 0; ks < 4; ks++) {
        uint32_t a0, a1, a2, a3;
        ldmA(aAddr + ks * 32, a0, a1, a2, a3);
        #pragma unroll
        for (int np = 0; np < 4; np++) {
            uint32_t b0, b1, b2, b3;
            ldmBT(bAddr + (uint32_t)(ks * 16 * STRIDE + np * 16) * 2, b0, b1, b2, b3);
            mma16816(cf[2 * np],     a0, a1, a2, a3, b0, b1);
            mma16816(cf[2 * np + 1], a0, a1, a2, a3, b2, b3);
        }
    }
}

// ---------------------------------------------------------------------------
// Adjacency build
// ---------------------------------------------------------------------------
__global__ void k_zero() {
    int n = blockIdx.x * blockDim.x + threadIdx.x;
    if (n < NN) g_cnt[n] = 0;
}
__global__ void k_build(const int* __restrict__ ei) {
    int e = blockIdx.x * blockDim.x + threadIdx.x;
    if (e < NE) {
        int u = ei[e];
        int p = ei[NE + e];
        int s1 = atomicAdd(&g_cnt[u], 1);
        if (s1 < CAP) g_adj[(size_t)u * CAP + s1] = p;   // message p -> u
        int s2 = atomicAdd(&g_cnt[p], 1);
        if (s2 < CAP) g_adj[(size_t)p * CAP + s2] = u;   // message u -> p
    }
}

// ---------------------------------------------------------------------------
// Feature projection (tensor core): g_xb[n] = bf16(feat[n](128) @ W + b + emb[n])
// Split grid: blocks [0,GU) users, [GU,GU+GP) products.
// ---------------------------------------------------------------------------
__global__ __launch_bounds__(256) void k_feat_t(
    const float* __restrict__ uf, const float* __restrict__ pf,
    const float* __restrict__ ue, const float* __restrict__ pe,
    const float* __restrict__ Wuf, const float* __restrict__ buf_,
    const float* __restrict__ Wpf, const float* __restrict__ bpf)
{
    __shared__ __align__(16) __nv_bfloat16 xt[128 * STRIDE];
    __shared__ __align__(16) __nv_bfloat16 wt[64 * STRIDE];
    __shared__ float bs[64];

    int bid = blockIdx.x;
    bool isUser = bid < GU;
    int lrow0 = isUser ? bid * 128 : (bid - GU) * 128;
    int nloc  = isUser ? NU : NP;
    const float* feat = isUser ? uf : pf;
    const float* emb  = isUser ? ue : pe;
    const float* W    = isUser ? Wuf : Wpf;
    const float* b    = isUser ? buf_ : bpf;
    int grow0 = isUser ? lrow0 : NU + lrow0;

    int tid = threadIdx.x;
    if (tid < 32) ((float2*)bs)[tid] = ((const float2*)b)[tid];

    int l = tid & 31, w = tid >> 5;
    float cf[8][4];
    #pragma unroll
    for (int j = 0; j < 8; j++)
        #pragma unroll
        for (int q = 0; q < 4; q++) cf[j][q] = 0.f;

    const float4* W4 = (const float4*)W;
    const float4* f4 = (const float4*)feat;   // row stride 32 float4

    #pragma unroll
    for (int ch = 0; ch < 2; ch++) {
        if (ch) __syncthreads();
        #pragma unroll
        for (int i = 0; i < 4; i++) {
            int idx = tid + i * 256, r = idx >> 4, c4 = idx & 15;
            float4 v = W4[ch * 1024 + idx];
            *(uint2*)(&wt[r * STRIDE + c4 * 4]) =
                make_uint2(pack_bf2(v.x, v.y), pack_bf2(v.z, v.w));
        }
        #pragma unroll
        for (int i = 0; i < 8; i++) {
            int idx = tid + i * 256, r = idx >> 4, c4 = idx & 15;
            int lr = lrow0 + r;
            float4 v = make_float4(0.f, 0.f, 0.f, 0.f);
            if (lr < nloc) v = f4[(size_t)lr * 32 + ch * 16 + c4];
            *(uint2*)(&xt[r * STRIDE + c4 * 4]) =
                make_uint2(pack_bf2(v.x, v.y), pack_bf2(v.z, v.w));
        }
        __syncthreads();
        mma_core((uint32_t)__cvta_generic_to_shared(xt) + (uint32_t)(w * 16 * STRIDE) * 2,
                 (uint32_t)__cvta_generic_to_shared(wt), l, cf);
    }

    int rl = w * 16 + (l >> 2);
    #pragma unroll
    for (int half = 0; half < 2; half++) {
        int lr = lrow0 + rl + half * 8;
        if (lr < nloc) {
            size_t gr = (size_t)(grow0 + rl + half * 8);
            #pragma unroll
            for (int j = 0; j < 8; j++) {
                int c2 = j * 4 + (l & 3);
                float2 ev = ((const float2*)emb)[(size_t)lr * 32 + c2];
                g_xb[gr * 32 + c2] = __floats2bfloat162_rn(
                    cf[j][half * 2 + 0] + bs[c2 * 2]     + ev.x,
                    cf[j][half * 2 + 1] + bs[c2 * 2 + 1] + ev.y);
            }
        }
    }
}

// ---------------------------------------------------------------------------
// k_mm: g_h[n] = (g_xb[n] @ W) * (epiDis ? dis[n] : 1)
// Split grid; Wu/Wp allow per-half weights (prednode). conv: Wu==Wp.
// ---------------------------------------------------------------------------
__global__ __launch_bounds__(256) void k_mm(
    const float* __restrict__ Wu, const float* __restrict__ Wp, int epiDis)
{
    __shared__ __align__(16) __nv_bfloat16 xt[128 * STRIDE];
    __shared__ __align__(16) __nv_bfloat16 wt[64 * STRIDE];

    int bid = blockIdx.x;
    bool isUser = bid < GU;
    int lrow0 = isUser ? bid * 128 : (bid - GU) * 128;
    int nloc  = isUser ? NU : NP;
    int grow0 = isUser ? lrow0 : NU + lrow0;
    const float* W = isUser ? Wu : Wp;

    int tid = threadIdx.x;
    #pragma unroll
    for (int i = 0; i < 4; i++) {
        int idx = tid + i * 256, r = idx >> 4, c4 = idx & 15;
        float4 v = ((const float4*)W)[idx];
        *(uint2*)(&wt[r * STRIDE + c4 * 4]) =
            make_uint2(pack_bf2(v.x, v.y), pack_bf2(v.z, v.w));
    }
    const uint4* x4 = (const uint4*)g_xb;
    #pragma unroll
    for (int i = 0; i < 4; i++) {
        int idx = tid + i * 256, r = idx >> 3, c = idx & 7;
        int lr = lrow0 + r;
        uint4 v = make_uint4(0u, 0u, 0u, 0u);
        if (lr < nloc) v = x4[(size_t)(grow0 + r) * 8 + c];
        *(uint4*)(&xt[r * STRIDE + c * 8]) = v;
    }
    __syncthreads();

    int l = tid & 31, w = tid >> 5;
    float cf[8][4];
    #pragma unroll
    for (int j = 0; j < 8; j++)
        #pragma unroll
        for (int q = 0; q < 4; q++) cf[j][q] = 0.f;

    mma_core((uint32_t)__cvta_generic_to_shared(xt) + (uint32_t)(w * 16 * STRIDE) * 2,
             (uint32_t)__cvta_generic_to_shared(wt), l, cf);

    int rl = w * 16 + (l >> 2);
    #pragma unroll
    for (int half = 0; half < 2; half++) {
        int lr = lrow0 + rl + half * 8;
        if (lr < nloc) {
            int gr = grow0 + rl + half * 8;
            float d = epiDis ? node_dis(gr) : 1.f;
            #pragma unroll
            for (int j = 0; j < 8; j++) {
                int c2 = j * 4 + (l & 3);
                g_h[(size_t)gr * 32 + c2] = __floats2bfloat162_rn(
                    cf[j][half * 2 + 0] * d, cf[j][half * 2 + 1] * d);
            }
        }
    }
}

// ---------------------------------------------------------------------------
// k_agg: g_xb[n] = act( b + dis[n] * (g_h[n] + sum_{src in adj[n]} g_h[src]) )
// One warp per node; coalesced 128B row reads; no atomics, no RMW.
// ---------------------------------------------------------------------------
__global__ __launch_bounds__(256) void k_agg(const float* __restrict__ b,
                                             int doRelu)
{
    int n = blockIdx.x * 8 + (threadIdx.x >> 5);
    if (n >= NN) return;
    int lane = threadIdx.x & 31;
    int c = g_cnt[n];
    if (c > CAP) c = CAP;
    float d = rsqrtf((float)(c + 1));
    const unsigned* hrow = (const unsigned*)g_h;
    unsigned own = hrow[(size_t)n * 32 + lane];
    float2 fo = __bfloat1622float2(*(__nv_bfloat162*)&own);
    float sx = fo.x, sy = fo.y;
    size_t base = (size_t)n * CAP;
    for (int i0 = 0; i0 < c; i0 += 32) {
        int m = min(32, c - i0);
        int srcl = (lane < m) ? g_adj[base + i0 + lane] : 0;
        int i = 0;
        for (; i + 1 < m; i += 2) {
            int s0 = __shfl_sync(0xffffffffu, srcl, i);
            int s1 = __shfl_sync(0xffffffffu, srcl, i + 1);
            unsigned r0 = hrow[(size_t)s0 * 32 + lane];
            unsigned r1 = hrow[(size_t)s1 * 32 + lane];
            float2 f0 = __bfloat1622float2(*(__nv_bfloat162*)&r0);
            float2 f1 = __bfloat1622float2(*(__nv_bfloat162*)&r1);
            sx += f0.x + f1.x;
            sy += f0.y + f1.y;
        }
        if (i < m) {
            int s0 = __shfl_sync(0xffffffffu, srcl, i);
            unsigned r0 = hrow[(size_t)s0 * 32 + lane];
            float2 f0 = __bfloat1622float2(*(__nv_bfloat162*)&r0);
            sx += f0.x;
            sy += f0.y;
        }
    }
    float2 bv = ((const float2*)b)[lane];
    float vx = bv.x + d * sx;
    float vy = bv.y + d * sy;
    if (doRelu) { vx = fmaxf(vx, 0.f); vy = fmaxf(vy, 0.f); }
    g_xb[(size_t)n * 32 + lane] = __floats2bfloat162_rn(vx, vy);
}

// ---------------------------------------------------------------------------
// k_prededge: h = relu(A[u]+B[p]+b1); out = 5*sigmoid(h.W2 + b2)
// 16 lanes per edge (2 edges/warp); coalesced uint2 row reads from g_h.
// ---------------------------------------------------------------------------
__global__ __launch_bounds__(256) void k_prededge(
    const int* __restrict__ ei,
    const float* __restrict__ b1, const float* __restrict__ W2,
    const float* __restrict__ b2, float* __restrict__ out)
{
    __shared__ float b1s[64], w2s[64];
    __shared__ float b2v;
    int tid = threadIdx.x;
    if (tid < 64) { b1s[tid] = b1[tid]; w2s[tid] = W2[tid]; }
    if (tid == 0) b2v = b2[0];
    __syncthreads();

    int e = blockIdx.x * 16 + (tid >> 4);
    if (e >= NE) return;
    int lg = tid & 15;
    int u = ei[e];
    int p = ei[NE + e];
    uint2 ar = ((const uint2*)g_h)[(size_t)u * 16 + lg];
    uint2 br = ((const uint2*)g_h)[(size_t)(NU + p) * 16 + lg];
    float2 a0 = __bfloat1622float2(*(__nv_bfloat162*)&ar.x);
    float2 a1 = __bfloat1622float2(*(__nv_bfloat162*)&ar.y);
    float2 c0 = __bfloat1622float2(*(__nv_bfloat162*)&br.x);
    float2 c1 = __bfloat1622float2(*(__nv_bfloat162*)&br.y);
    float4 b1v = ((const float4*)b1s)[lg];
    float4 w2v = ((const float4*)w2s)[lg];
    float h0 = fmaxf(a0.x + c0.x + b1v.x, 0.f);
    float h1 = fmaxf(a0.y + c0.y + b1v.y, 0.f);
    float h2 = fmaxf(a1.x + c1.x + b1v.z, 0.f);
    float h3 = fmaxf(a1.y + c1.y + b1v.w, 0.f);
    float part = h0 * w2v.x + h1 * w2v.y + h2 * w2v.z + h3 * w2v.w;
    #pragma unroll
    for (int off = 8; off; off >>= 1)
        part += __shfl_xor_sync(0xffffffffu, part, off);
    if (lg == 0) {
        float z = part + b2v;
        out[e] = 5.f / (1.f + expf(-z));
    }
}

// ---------------------------------------------------------------------------
extern "C" void kernel_launch(void* const* d_in, const int* in_sizes, int n_in,
                              void* d_out, int out_size)
{
    const int*   ei  = (const int*)d_in[0];   // [2, NE] int32
    const float* uf  = (const float*)d_in[1];
    const float* pf  = (const float*)d_in[2];
    const float* ue  = (const float*)d_in[3];
    const float* pe  = (const float*)d_in[4];
    const float* Wuf = (const float*)d_in[5];
    const float* buf_= (const float*)d_in[6];
    const float* Wpf = (const float*)d_in[7];
    const float* bpf = (const float*)d_in[8];
    const float* c1W = (const float*)d_in[9];
    const float* c1b = (const float*)d_in[10];
    const float* c2W = (const float*)d_in[11];
    const float* c2b = (const float*)d_in[12];
    const float* pW1 = (const float*)d_in[13];
    const float* pb1 = (const float*)d_in[14];
    const float* pW2 = (const float*)d_in[15];
    const float* pb2 = (const float*)d_in[16];
    float* out = (float*)d_out;

    k_zero <<<(NN + 255) / 256, 256>>>();
    k_build<<<(NE + 255) / 256, 256>>>(ei);

    // x -> g_xb
    k_feat_t<<<GU + GP, 256>>>(uf, pf, ue, pe, Wuf, buf_, Wpf, bpf);

    // conv1: hs1 = (x @ c1W) * d -> g_h;  xin2 = relu(c1b + d*(own+sum)) -> g_xb
    k_mm <<<GU + GP, 256>>>(c1W, c1W, 1);
    k_agg<<<NN / 8, 256>>>(c1b, 1);

    // conv2: hs2 = (xin2 @ c2W) * d -> g_h;  xin3 = c2b + d*(own+sum) -> g_xb
    k_mm <<<GU + GP, 256>>>(c2W, c2W, 1);
    k_agg<<<NN / 8, 256>>>(c2b, 0);

    // prednode: projections = xin3 @ W1half -> g_h
    k_mm <<<GU + GP, 256>>>(pW1, pW1 + 4096, 0);

    // per-edge combine
    k_prededge<<<NE / 16, 256>>>(ei, pb1, pW2, pb2, out);
}

// round 10
// speedup vs baseline: 1.3051x; 1.0638x over previous
#include <cuda_runtime.h>
#include <cuda_bf16.h>
#include <cstdint>
#include <math.h>

#define NU 200000
#define NP 100000
#define NN 300000
#define NE 1000000
#define CAP 64             // adjacency slots per node (Poisson(~6.7): overflow impossible)
#define STRIDE 72          // bf16 units, padded row stride for smem tiles
#define GU 1563            // ceil(NU/128)
#define GP 782             // ceil(NP/128)

// Scratch (module-static device memory; sanctioned by harness rules)
__device__ __nv_bfloat162 g_xb[(size_t)NN * 32];   // GEMM inputs (x / activated conv out)
__device__ __nv_bfloat162 g_h [(size_t)NN * 32];   // messages / pred projections
__device__ int            g_cnt[NN];
__device__ int            g_adj[(size_t)NN * CAP];

// ---------------------------------------------------------------------------
// helpers
// ---------------------------------------------------------------------------
__device__ __forceinline__ unsigned pack_bf2(float x, float y) {
    __nv_bfloat162 h = __floats2bfloat162_rn(x, y);
    return *(unsigned*)&h;
}
__device__ __forceinline__ float node_dis(int n) {
    return rsqrtf((float)(g_cnt[n] + 1));   // +1 self loop
}

__device__ __forceinline__ void ldmA(uint32_t addr, uint32_t& a0, uint32_t& a1,
                                     uint32_t& a2, uint32_t& a3) {
    asm volatile("ldmatrix.sync.aligned.m8n8.x4.shared.b16 {%0,%1,%2,%3},[%4];"
                 : "=r"(a0), "=r"(a1), "=r"(a2), "=r"(a3) : "r"(addr));
}
__device__ __forceinline__ void ldmBT(uint32_t addr, uint32_t& b0, uint32_t& b1,
                                      uint32_t& b2, uint32_t& b3) {
    asm volatile("ldmatrix.sync.aligned.m8n8.x4.trans.shared.b16 {%0,%1,%2,%3},[%4];"
                 : "=r"(b0), "=r"(b1), "=r"(b2), "=r"(b3) : "r"(addr));
}
__device__ __forceinline__ void mma16816(float* c, uint32_t a0, uint32_t a1,
                                         uint32_t a2, uint32_t a3,
                                         uint32_t b0, uint32_t b1) {
    asm volatile("mma.sync.aligned.m16n8k16.row.col.f32.bf16.bf16.f32 "
                 "{%0,%1,%2,%3},{%4,%5,%6,%7},{%8,%9},{%0,%1,%2,%3};"
                 : "+f"(c[0]), "+f"(c[1]), "+f"(c[2]), "+f"(c[3])
                 : "r"(a0), "r"(a1), "r"(a2), "r"(a3), "r"(b0), "r"(b1));
}

// One K=64 chunk: C[warp 16 rows x 64 cols] += xt_warp[16x64] @ wt[64x64]
__device__ __forceinline__ void mma_core(uint32_t xtw, uint32_t wtb, int l,
                                         float cf[8][4]) {
    uint32_t rowOff = (uint32_t)(((l & 7) + ((l >> 3) & 1) * 8) * STRIDE + (l >> 4) * 8) * 2;
    uint32_t aAddr = xtw + rowOff;
    uint32_t bAddr = wtb + rowOff;
    #pragma unroll
    for (int ks = 0; ks < 4; ks++) {
        uint32_t a0, a1, a2, a3;
        ldmA(aAddr + ks * 32, a0, a1, a2, a3);
        #pragma unroll
        for (int np = 0; np < 4; np++) {
            uint32_t b0, b1, b2, b3;
            ldmBT(bAddr + (uint32_t)(ks * 16 * STRIDE + np * 16) * 2, b0, b1, b2, b3);
            mma16816(cf[2 * np],     a0, a1, a2, a3, b0, b1);
            mma16816(cf[2 * np + 1], a0, a1, a2, a3, b2, b3);
        }
    }
}

// ---------------------------------------------------------------------------
// Adjacency build
// ---------------------------------------------------------------------------
__global__ void k_zero() {
    int n = blockIdx.x * blockDim.x + threadIdx.x;
    if (n < NN) g_cnt[n] = 0;
}
__global__ void k_build(const int* __restrict__ ei) {
    int e = blockIdx.x * blockDim.x + threadIdx.x;
    if (e < NE) {
        int u = ei[e];
        int p = ei[NE + e];
        int s1 = atomicAdd(&g_cnt[u], 1);
        if (s1 < CAP) g_adj[(size_t)u * CAP + s1] = p;   // message p -> u
        int s2 = atomicAdd(&g_cnt[p], 1);
        if (s2 < CAP) g_adj[(size_t)p * CAP + s2] = u;   // message u -> p
    }
}

// ---------------------------------------------------------------------------
// Feature projection (tensor core): g_xb[n] = bf16(feat[n](128) @ W + b + emb[n])
// Split grid: blocks [0,GU) users, [GU,GU+GP) products.
// ---------------------------------------------------------------------------
__global__ __launch_bounds__(256, 3) void k_feat_t(
    const float* __restrict__ uf, const float* __restrict__ pf,
    const float* __restrict__ ue, const float* __restrict__ pe,
    const float* __restrict__ Wuf, const float* __restrict__ buf_,
    const float* __restrict__ Wpf, const float* __restrict__ bpf)
{
    __shared__ __align__(16) __nv_bfloat16 xt[128 * STRIDE];
    __shared__ __align__(16) __nv_bfloat16 wt[64 * STRIDE];
    __shared__ float bs[64];

    int bid = blockIdx.x;
    bool isUser = bid < GU;
    int lrow0 = isUser ? bid * 128 : (bid - GU) * 128;
    int nloc  = isUser ? NU : NP;
    const float* feat = isUser ? uf : pf;
    const float* emb  = isUser ? ue : pe;
    const float* W    = isUser ? Wuf : Wpf;
    const float* b    = isUser ? buf_ : bpf;
    int grow0 = isUser ? lrow0 : NU + lrow0;

    int tid = threadIdx.x;
    if (tid < 32) ((float2*)bs)[tid] = ((const float2*)b)[tid];

    int l = tid & 31, w = tid >> 5;
    float cf[8][4];
    #pragma unroll
    for (int j = 0; j < 8; j++)
        #pragma unroll
        for (int q = 0; q < 4; q++) cf[j][q] = 0.f;

    const float4* W4 = (const float4*)W;
    const float4* f4 = (const float4*)feat;   // row stride 32 float4

    #pragma unroll
    for (int ch = 0; ch < 2; ch++) {
        if (ch) __syncthreads();
        #pragma unroll
        for (int i = 0; i < 4; i++) {
            int idx = tid + i * 256, r = idx >> 4, c4 = idx & 15;
            float4 v = W4[ch * 1024 + idx];
            *(uint2*)(&wt[r * STRIDE + c4 * 4]) =
                make_uint2(pack_bf2(v.x, v.y), pack_bf2(v.z, v.w));
        }
        #pragma unroll
        for (int i = 0; i < 8; i++) {
            int idx = tid + i * 256, r = idx >> 4, c4 = idx & 15;
            int lr = lrow0 + r;
            float4 v = make_float4(0.f, 0.f, 0.f, 0.f);
            if (lr < nloc) v = f4[(size_t)lr * 32 + ch * 16 + c4];
            *(uint2*)(&xt[r * STRIDE + c4 * 4]) =
                make_uint2(pack_bf2(v.x, v.y), pack_bf2(v.z, v.w));
        }
        __syncthreads();
        mma_core((uint32_t)__cvta_generic_to_shared(xt) + (uint32_t)(w * 16 * STRIDE) * 2,
                 (uint32_t)__cvta_generic_to_shared(wt), l, cf);
    }

    int rl = w * 16 + (l >> 2);
    #pragma unroll
    for (int half = 0; half < 2; half++) {
        int lr = lrow0 + rl + half * 8;
        if (lr < nloc) {
            size_t gr = (size_t)(grow0 + rl + half * 8);
            #pragma unroll
            for (int j = 0; j < 8; j++) {
                int c2 = j * 4 + (l & 3);
                float2 ev = ((const float2*)emb)[(size_t)lr * 32 + c2];
                g_xb[gr * 32 + c2] = __floats2bfloat162_rn(
                    cf[j][half * 2 + 0] + bs[c2 * 2]     + ev.x,
                    cf[j][half * 2 + 1] + bs[c2 * 2 + 1] + ev.y);
            }
        }
    }
}

// ---------------------------------------------------------------------------
// k_mm: g_h[n] = (g_xb[n] @ W) * (epiDis ? dis[n] : 1)
// Split grid; Wu/Wp allow per-half weights (prednode). conv: Wu==Wp.
// ---------------------------------------------------------------------------
__global__ __launch_bounds__(256) void k_mm(
    const float* __restrict__ Wu, const float* __restrict__ Wp, int epiDis)
{
    __shared__ __align__(16) __nv_bfloat16 xt[128 * STRIDE];
    __shared__ __align__(16) __nv_bfloat16 wt[64 * STRIDE];

    int bid = blockIdx.x;
    bool isUser = bid < GU;
    int lrow0 = isUser ? bid * 128 : (bid - GU) * 128;
    int nloc  = isUser ? NU : NP;
    int grow0 = isUser ? lrow0 : NU + lrow0;
    const float* W = isUser ? Wu : Wp;

    int tid = threadIdx.x;
    #pragma unroll
    for (int i = 0; i < 4; i++) {
        int idx = tid + i * 256, r = idx >> 4, c4 = idx & 15;
        float4 v = ((const float4*)W)[idx];
        *(uint2*)(&wt[r * STRIDE + c4 * 4]) =
            make_uint2(pack_bf2(v.x, v.y), pack_bf2(v.z, v.w));
    }
    const uint4* x4 = (const uint4*)g_xb;
    #pragma unroll
    for (int i = 0; i < 4; i++) {
        int idx = tid + i * 256, r = idx >> 3, c = idx & 7;
        int lr = lrow0 + r;
        uint4 v = make_uint4(0u, 0u, 0u, 0u);
        if (lr < nloc) v = x4[(size_t)(grow0 + r) * 8 + c];
        *(uint4*)(&xt[r * STRIDE + c * 8]) = v;
    }
    __syncthreads();

    int l = tid & 31, w = tid >> 5;
    float cf[8][4];
    #pragma unroll
    for (int j = 0; j < 8; j++)
        #pragma unroll
        for (int q = 0; q < 4; q++) cf[j][q] = 0.f;

    mma_core((uint32_t)__cvta_generic_to_shared(xt) + (uint32_t)(w * 16 * STRIDE) * 2,
             (uint32_t)__cvta_generic_to_shared(wt), l, cf);

    int rl = w * 16 + (l >> 2);
    #pragma unroll
    for (int half = 0; half < 2; half++) {
        int lr = lrow0 + rl + half * 8;
        if (lr < nloc) {
            int gr = grow0 + rl + half * 8;
            float d = epiDis ? node_dis(gr) : 1.f;
            #pragma unroll
            for (int j = 0; j < 8; j++) {
                int c2 = j * 4 + (l & 3);
                g_h[(size_t)gr * 32 + c2] = __floats2bfloat162_rn(
                    cf[j][half * 2 + 0] * d, cf[j][half * 2 + 1] * d);
            }
        }
    }
}

// ---------------------------------------------------------------------------
// k_agg: g_xb[n] = act( b + dis[n] * (g_h[n] + sum_{src in adj[n]} g_h[src]) )
// One warp per node; coalesced 128B row reads; 4-way unrolled neighbor fetch.
// ---------------------------------------------------------------------------
__global__ __launch_bounds__(256) void k_agg(const float* __restrict__ b,
                                             int doRelu)
{
    int n = blockIdx.x * 8 + (threadIdx.x >> 5);
    if (n >= NN) return;
    int lane = threadIdx.x & 31;
    int c = g_cnt[n];
    if (c > CAP) c = CAP;
    float d = rsqrtf((float)(c + 1));
    const unsigned* hrow = (const unsigned*)g_h;
    unsigned own = hrow[(size_t)n * 32 + lane];
    float2 fo = __bfloat1622float2(*(__nv_bfloat162*)&own);
    float sx = fo.x, sy = fo.y;
    size_t base = (size_t)n * CAP;
    for (int i0 = 0; i0 < c; i0 += 32) {
        int m = min(32, c - i0);
        int srcl = (lane < m) ? g_adj[base + i0 + lane] : 0;
        int i = 0;
        for (; i + 3 < m; i += 4) {
            int s0 = __shfl_sync(0xffffffffu, srcl, i);
            int s1 = __shfl_sync(0xffffffffu, srcl, i + 1);
            int s2 = __shfl_sync(0xffffffffu, srcl, i + 2);
            int s3 = __shfl_sync(0xffffffffu, srcl, i + 3);
            unsigned r0 = hrow[(size_t)s0 * 32 + lane];
            unsigned r1 = hrow[(size_t)s1 * 32 + lane];
            unsigned r2 = hrow[(size_t)s2 * 32 + lane];
            unsigned r3 = hrow[(size_t)s3 * 32 + lane];
            float2 f0 = __bfloat1622float2(*(__nv_bfloat162*)&r0);
            float2 f1 = __bfloat1622float2(*(__nv_bfloat162*)&r1);
            float2 f2 = __bfloat1622float2(*(__nv_bfloat162*)&r2);
            float2 f3 = __bfloat1622float2(*(__nv_bfloat162*)&r3);
            sx += (f0.x + f1.x) + (f2.x + f3.x);
            sy += (f0.y + f1.y) + (f2.y + f3.y);
        }
        for (; i + 1 < m; i += 2) {
            int s0 = __shfl_sync(0xffffffffu, srcl, i);
            int s1 = __shfl_sync(0xffffffffu, srcl, i + 1);
            unsigned r0 = hrow[(size_t)s0 * 32 + lane];
            unsigned r1 = hrow[(size_t)s1 * 32 + lane];
            float2 f0 = __bfloat1622float2(*(__nv_bfloat162*)&r0);
            float2 f1 = __bfloat1622float2(*(__nv_bfloat162*)&r1);
            sx += f0.x + f1.x;
            sy += f0.y + f1.y;
        }
        if (i < m) {
            int s0 = __shfl_sync(0xffffffffu, srcl, i);
            unsigned r0 = hrow[(size_t)s0 * 32 + lane];
            float2 f0 = __bfloat1622float2(*(__nv_bfloat162*)&r0);
            sx += f0.x;
            sy += f0.y;
        }
    }
    float2 bv = ((const float2*)b)[lane];
    float vx = bv.x + d * sx;
    float vy = bv.y + d * sy;
    if (doRelu) { vx = fmaxf(vx, 0.f); vy = fmaxf(vy, 0.f); }
    g_xb[(size_t)n * 32 + lane] = __floats2bfloat162_rn(vx, vy);
}

// ---------------------------------------------------------------------------
// k_prededge: h = relu(A[u]+B[p]+b1); out = 5*sigmoid(h.W2 + b2)
// 8 lanes per edge (4 edges/warp); uint4 row reads (16B/lane) for high MLP.
// ---------------------------------------------------------------------------
__global__ __launch_bounds__(256) void k_prededge(
    const int* __restrict__ ei,
    const float* __restrict__ b1, const float* __restrict__ W2,
    const float* __restrict__ b2, float* __restrict__ out)
{
    __shared__ float b1s[64], w2s[64];
    __shared__ float b2v;
    int tid = threadIdx.x;
    if (tid < 64) { b1s[tid] = b1[tid]; w2s[tid] = W2[tid]; }
    if (tid == 0) b2v = b2[0];
    __syncthreads();

    int e = blockIdx.x * 32 + (tid >> 3);
    if (e >= NE) return;
    int lg = tid & 7;            // 8 lanes/edge, 8 bf16 cols per lane
    int u = ei[e];
    int p = ei[NE + e];
    uint4 ar = ((const uint4*)g_h)[(size_t)u * 8 + lg];
    uint4 br = ((const uint4*)g_h)[(size_t)(NU + p) * 8 + lg];
    float4 b1a = ((const float4*)b1s)[lg * 2];
    float4 b1b = ((const float4*)b1s)[lg * 2 + 1];
    float4 w2a = ((const float4*)w2s)[lg * 2];
    float4 w2b = ((const float4*)w2s)[lg * 2 + 1];
    float2 a0 = __bfloat1622float2(*(__nv_bfloat162*)&ar.x);
    float2 a1 = __bfloat1622float2(*(__nv_bfloat162*)&ar.y);
    float2 a2 = __bfloat1622float2(*(__nv_bfloat162*)&ar.z);
    float2 a3 = __bfloat1622float2(*(__nv_bfloat162*)&ar.w);
    float2 c0 = __bfloat1622float2(*(__nv_bfloat162*)&br.x);
    float2 c1 = __bfloat1622float2(*(__nv_bfloat162*)&br.y);
    float2 c2 = __bfloat1622float2(*(__nv_bfloat162*)&br.z);
    float2 c3 = __bfloat1622float2(*(__nv_bfloat162*)&br.w);
    float h0 = fmaxf(a0.x + c0.x + b1a.x, 0.f);
    float h1 = fmaxf(a0.y + c0.y + b1a.y, 0.f);
    float h2 = fmaxf(a1.x + c1.x + b1a.z, 0.f);
    float h3 = fmaxf(a1.y + c1.y + b1a.w, 0.f);
    float h4 = fmaxf(a2.x + c2.x + b1b.x, 0.f);
    float h5 = fmaxf(a2.y + c2.y + b1b.y, 0.f);
    float h6 = fmaxf(a3.x + c3.x + b1b.z, 0.f);
    float h7 = fmaxf(a3.y + c3.y + b1b.w, 0.f);
    float part = (h0 * w2a.x + h1 * w2a.y + h2 * w2a.z + h3 * w2a.w)
               + (h4 * w2b.x + h5 * w2b.y + h6 * w2b.z + h7 * w2b.w);
    #pragma unroll
    for (int off = 4; off; off >>= 1)
        part += __shfl_xor_sync(0xffffffffu, part, off);
    if (lg == 0) {
        float z = part + b2v;
        out[e] = 5.f / (1.f + expf(-z));
    }
}

// ---------------------------------------------------------------------------
extern "C" void kernel_launch(void* const* d_in, const int* in_sizes, int n_in,
                              void* d_out, int out_size)
{
    const int*   ei  = (const int*)d_in[0];   // [2, NE] int32
    const float* uf  = (const float*)d_in[1];
    const float* pf  = (const float*)d_in[2];
    const float* ue  = (const float*)d_in[3];
    const float* pe  = (const float*)d_in[4];
    const float* Wuf = (const float*)d_in[5];
    const float* buf_= (const float*)d_in[6];
    const float* Wpf = (const float*)d_in[7];
    const float* bpf = (const float*)d_in[8];
    const float* c1W = (const float*)d_in[9];
    const float* c1b = (const float*)d_in[10];
    const float* c2W = (const float*)d_in[11];
    const float* c2b = (const float*)d_in[12];
    const float* pW1 = (const float*)d_in[13];
    const float* pb1 = (const float*)d_in[14];
    const float* pW2 = (const float*)d_in[15];
    const float* pb2 = (const float*)d_in[16];
    float* out = (float*)d_out;

    k_zero <<<(NN + 255) / 256, 256>>>();
    k_build<<<(NE + 255) / 256, 256>>>(ei);

    // x -> g_xb
    k_feat_t<<<GU + GP, 256>>>(uf, pf, ue, pe, Wuf, buf_, Wpf, bpf);

    // conv1: hs1 = (x @ c1W) * d -> g_h;  xin2 = relu(c1b + d*(own+sum)) -> g_xb
    k_mm <<<GU + GP, 256>>>(c1W, c1W, 1);
    k_agg<<<NN / 8, 256>>>(c1b, 1);

    // conv2: hs2 = (xin2 @ c2W) * d -> g_h;  xin3 = c2b + d*(own+sum) -> g_xb
    k_mm <<<GU + GP, 256>>>(c2W, c2W, 1);
    k_agg<<<NN / 8, 256>>>(c2b, 0);

    // prednode: projections = xin3 @ W1half -> g_h
    k_mm <<<GU + GP, 256>>>(pW1, pW1 + 4096, 0);

    // per-edge combine
    k_prededge<<<NE / 32, 256>>>(ei, pb1, pW2, pb2, out);
}

// round 11
// speedup vs baseline: 1.4023x; 1.0744x over previous
#include <cuda_runtime.h>
#include <cuda_bf16.h>
#include <cuda_fp8.h>
#include <cstdint>
#include <math.h>

#define NU 200000
#define NP 100000
#define NN 300000
#define NE 1000000
#define CAP 64             // adjacency slots per node (Poisson(~6.7): overflow impossible)
#define STRIDE 72          // bf16 units, padded row stride for smem tiles
#define GU 1563            // ceil(NU/128)
#define GP 782             // ceil(NP/128)

// Scratch (module-static device memory; sanctioned by harness rules)
__device__ __nv_bfloat162 g_xb[(size_t)NN * 32];     // GEMM inputs (bf16)
__device__ unsigned short g_h8[(size_t)NN * 32];     // messages / projections (fp8x2 e4m3)
__device__ int            g_cnt[NN];
__device__ int            g_adj[(size_t)NN * CAP];

// ---------------------------------------------------------------------------
// helpers
// ---------------------------------------------------------------------------
__device__ __forceinline__ unsigned pack_bf2(float x, float y) {
    __nv_bfloat162 h = __floats2bfloat162_rn(x, y);
    return *(unsigned*)&h;
}
__device__ __forceinline__ unsigned short f2_to_fp8x2(float x, float y) {
    float2 f = make_float2(x, y);
    return (unsigned short)__nv_cvt_float2_to_fp8x2(f, __NV_SATFINITE, __NV_E4M3);
}
__device__ __forceinline__ float2 fp8x2_to_f2(unsigned short v) {
    __half2_raw hr = __nv_cvt_fp8x2_to_halfraw2((__nv_fp8x2_storage_t)v, __NV_E4M3);
    return __half22float2(*(__half2*)&hr);
}

__device__ __forceinline__ void ldmA(uint32_t addr, uint32_t& a0, uint32_t& a1,
                                     uint32_t& a2, uint32_t& a3) {
    asm volatile("ldmatrix.sync.aligned.m8n8.x4.shared.b16 {%0,%1,%2,%3},[%4];"
                 : "=r"(a0), "=r"(a1), "=r"(a2), "=r"(a3) : "r"(addr));
}
__device__ __forceinline__ void ldmBT(uint32_t addr, uint32_t& b0, uint32_t& b1,
                                      uint32_t& b2, uint32_t& b3) {
    asm volatile("ldmatrix.sync.aligned.m8n8.x4.trans.shared.b16 {%0,%1,%2,%3},[%4];"
                 : "=r"(b0), "=r"(b1), "=r"(b2), "=r"(b3) : "r"(addr));
}
__device__ __forceinline__ void mma16816(float* c, uint32_t a0, uint32_t a1,
                                         uint32_t a2, uint32_t a3,
                                         uint32_t b0, uint32_t b1) {
    asm volatile("mma.sync.aligned.m16n8k16.row.col.f32.bf16.bf16.f32 "
                 "{%0,%1,%2,%3},{%4,%5,%6,%7},{%8,%9},{%0,%1,%2,%3};"
                 : "+f"(c[0]), "+f"(c[1]), "+f"(c[2]), "+f"(c[3])
                 : "r"(a0), "r"(a1), "r"(a2), "r"(a3), "r"(b0), "r"(b1));
}

// One K=64 chunk: C[warp 16 rows x 64 cols] += xt_warp[16x64] @ wt[64x64]
__device__ __forceinline__ void mma_core(uint32_t xtw, uint32_t wtb, int l,
                                         float cf[8][4]) {
    uint32_t rowOff = (uint32_t)(((l & 7) + ((l >> 3) & 1) * 8) * STRIDE + (l >> 4) * 8) * 2;
    uint32_t aAddr = xtw + rowOff;
    uint32_t bAddr = wtb + rowOff;
    #pragma unroll
    for (int ks = 0; ks < 4; ks++) {
        uint32_t a0, a1, a2, a3;
        ldmA(aAddr + ks * 32, a0, a1, a2, a3);
        #pragma unroll
        for (int np = 0; np < 4; np++) {
            uint32_t b0, b1, b2, b3;
            ldmBT(bAddr + (uint32_t)(ks * 16 * STRIDE + np * 16) * 2, b0, b1, b2, b3);
            mma16816(cf[2 * np],     a0, a1, a2, a3, b0, b1);
            mma16816(cf[2 * np + 1], a0, a1, a2, a3, b2, b3);
        }
    }
}

// ---------------------------------------------------------------------------
// Adjacency build
// ---------------------------------------------------------------------------
__global__ void k_zero() {
    int n = blockIdx.x * blockDim.x + threadIdx.x;
    if (n < NN) g_cnt[n] = 0;
}
__global__ void k_build(const int* __restrict__ ei) {
    int e = blockIdx.x * blockDim.x + threadIdx.x;
    if (e < NE) {
        int u = ei[e];
        int p = ei[NE + e];
        int s1 = atomicAdd(&g_cnt[u], 1);
        if (s1 < CAP) g_adj[(size_t)u * CAP + s1] = p;   // message p -> u
        int s2 = atomicAdd(&g_cnt[p], 1);
        if (s2 < CAP) g_adj[(size_t)p * CAP + s2] = u;   // message u -> p
    }
}

// ---------------------------------------------------------------------------
// Feature projection (tensor core): g_xb[n] = bf16(feat[n](128) @ W + b + emb[n])
// Split grid: blocks [0,GU) users, [GU,GU+GP) products.
// ---------------------------------------------------------------------------
__global__ __launch_bounds__(256, 3) void k_feat_t(
    const float* __restrict__ uf, const float* __restrict__ pf,
    const float* __restrict__ ue, const float* __restrict__ pe,
    const float* __restrict__ Wuf, const float* __restrict__ buf_,
    const float* __restrict__ Wpf, const float* __restrict__ bpf)
{
    __shared__ __align__(16) __nv_bfloat16 xt[128 * STRIDE];
    __shared__ __align__(16) __nv_bfloat16 wt[64 * STRIDE];
    __shared__ float bs[64];

    int bid = blockIdx.x;
    bool isUser = bid < GU;
    int lrow0 = isUser ? bid * 128 : (bid - GU) * 128;
    int nloc  = isUser ? NU : NP;
    const float* feat = isUser ? uf : pf;
    const float* emb  = isUser ? ue : pe;
    const float* W    = isUser ? Wuf : Wpf;
    const float* b    = isUser ? buf_ : bpf;
    int grow0 = isUser ? lrow0 : NU + lrow0;

    int tid = threadIdx.x;
    if (tid < 32) ((float2*)bs)[tid] = ((const float2*)b)[tid];

    int l = tid & 31, w = tid >> 5;
    float cf[8][4];
    #pragma unroll
    for (int j = 0; j < 8; j++)
        #pragma unroll
        for (int q = 0; q < 4; q++) cf[j][q] = 0.f;

    const float4* W4 = (const float4*)W;
    const float4* f4 = (const float4*)feat;   // row stride 32 float4

    #pragma unroll
    for (int ch = 0; ch < 2; ch++) {
        if (ch) __syncthreads();
        #pragma unroll
        for (int i = 0; i < 4; i++) {
            int idx = tid + i * 256, r = idx >> 4, c4 = idx & 15;
            float4 v = W4[ch * 1024 + idx];
            *(uint2*)(&wt[r * STRIDE + c4 * 4]) =
                make_uint2(pack_bf2(v.x, v.y), pack_bf2(v.z, v.w));
        }
        #pragma unroll
        for (int i = 0; i < 8; i++) {
            int idx = tid + i * 256, r = idx >> 4, c4 = idx & 15;
            int lr = lrow0 + r;
            float4 v = make_float4(0.f, 0.f, 0.f, 0.f);
            if (lr < nloc) v = f4[(size_t)lr * 32 + ch * 16 + c4];
            *(uint2*)(&xt[r * STRIDE + c4 * 4]) =
                make_uint2(pack_bf2(v.x, v.y), pack_bf2(v.z, v.w));
        }
        __syncthreads();
        mma_core((uint32_t)__cvta_generic_to_shared(xt) + (uint32_t)(w * 16 * STRIDE) * 2,
                 (uint32_t)__cvta_generic_to_shared(wt), l, cf);
    }

    int rl = w * 16 + (l >> 2);
    #pragma unroll
    for (int half = 0; half < 2; half++) {
        int lr = lrow0 + rl + half * 8;
        if (lr < nloc) {
            size_t gr = (size_t)(grow0 + rl + half * 8);
            #pragma unroll
            for (int j = 0; j < 8; j++) {
                int c2 = j * 4 + (l & 3);
                float2 ev = ((const float2*)emb)[(size_t)lr * 32 + c2];
                g_xb[gr * 32 + c2] = __floats2bfloat162_rn(
                    cf[j][half * 2 + 0] + bs[c2 * 2]     + ev.x,
                    cf[j][half * 2 + 1] + bs[c2 * 2 + 1] + ev.y);
            }
        }
    }
}

// ---------------------------------------------------------------------------
// k_mm: g_h8[n] = fp8( (g_xb[n] @ W) * (epiDis ? dis[n] : 1) )
// Split grid; Wu/Wp allow per-half weights (prednode). conv: Wu==Wp.
// ---------------------------------------------------------------------------
__global__ __launch_bounds__(256) void k_mm(
    const float* __restrict__ Wu, const float* __restrict__ Wp, int epiDis)
{
    __shared__ __align__(16) __nv_bfloat16 xt[128 * STRIDE];
    __shared__ __align__(16) __nv_bfloat16 wt[64 * STRIDE];

    int bid = blockIdx.x;
    bool isUser = bid < GU;
    int lrow0 = isUser ? bid * 128 : (bid - GU) * 128;
    int nloc  = isUser ? NU : NP;
    int grow0 = isUser ? lrow0 : NU + lrow0;
    const float* W = isUser ? Wu : Wp;

    int tid = threadIdx.x;
    #pragma unroll
    for (int i = 0; i < 4; i++) {
        int idx = tid + i * 256, r = idx >> 4, c4 = idx & 15;
        float4 v = ((const float4*)W)[idx];
        *(uint2*)(&wt[r * STRIDE + c4 * 4]) =
            make_uint2(pack_bf2(v.x, v.y), pack_bf2(v.z, v.w));
    }
    const uint4* x4 = (const uint4*)g_xb;
    #pragma unroll
    for (int i = 0; i < 4; i++) {
        int idx = tid + i * 256, r = idx >> 3, c = idx & 7;
        int lr = lrow0 + r;
        uint4 v = make_uint4(0u, 0u, 0u, 0u);
        if (lr < nloc) v = x4[(size_t)(grow0 + r) * 8 + c];
        *(uint4*)(&xt[r * STRIDE + c * 8]) = v;
    }
    __syncthreads();

    int l = tid & 31, w = tid >> 5;
    float cf[8][4];
    #pragma unroll
    for (int j = 0; j < 8; j++)
        #pragma unroll
        for (int q = 0; q < 4; q++) cf[j][q] = 0.f;

    mma_core((uint32_t)__cvta_generic_to_shared(xt) + (uint32_t)(w * 16 * STRIDE) * 2,
             (uint32_t)__cvta_generic_to_shared(wt), l, cf);

    int rl = w * 16 + (l >> 2);
    #pragma unroll
    for (int half = 0; half < 2; half++) {
        int lr = lrow0 + rl + half * 8;
        if (lr < nloc) {
            int gr = grow0 + rl + half * 8;
            float d = epiDis ? rsqrtf((float)(g_cnt[gr] + 1)) : 1.f;
            #pragma unroll
            for (int j = 0; j < 8; j++) {
                int c2 = j * 4 + (l & 3);
                g_h8[(size_t)gr * 32 + c2] = f2_to_fp8x2(
                    cf[j][half * 2 + 0] * d, cf[j][half * 2 + 1] * d);
            }
        }
    }
}

// ---------------------------------------------------------------------------
// k_agg: g_xb[n] = act( b + dis[n] * (g_h8[n] + sum_{src in adj[n]} g_h8[src]) )
// One warp per node; coalesced 64B row reads; 4-way unrolled neighbor fetch.
// ---------------------------------------------------------------------------
__global__ __launch_bounds__(256) void k_agg(const float* __restrict__ b,
                                             int doRelu)
{
    int n = blockIdx.x * 8 + (threadIdx.x >> 5);
    if (n >= NN) return;
    int lane = threadIdx.x & 31;
    int c = g_cnt[n];
    if (c > CAP) c = CAP;
    float d = rsqrtf((float)(c + 1));
    float2 fo = fp8x2_to_f2(g_h8[(size_t)n * 32 + lane]);
    float sx = fo.x, sy = fo.y;
    size_t base = (size_t)n * CAP;
    for (int i0 = 0; i0 < c; i0 += 32) {
        int m = min(32, c - i0);
        int srcl = (lane < m) ? g_adj[base + i0 + lane] : 0;
        int i = 0;
        for (; i + 3 < m; i += 4) {
            int s0 = __shfl_sync(0xffffffffu, srcl, i);
            int s1 = __shfl_sync(0xffffffffu, srcl, i + 1);
            int s2 = __shfl_sync(0xffffffffu, srcl, i + 2);
            int s3 = __shfl_sync(0xffffffffu, srcl, i + 3);
            unsigned short r0 = g_h8[(size_t)s0 * 32 + lane];
            unsigned short r1 = g_h8[(size_t)s1 * 32 + lane];
            unsigned short r2 = g_h8[(size_t)s2 * 32 + lane];
            unsigned short r3 = g_h8[(size_t)s3 * 32 + lane];
            float2 f0 = fp8x2_to_f2(r0);
            float2 f1 = fp8x2_to_f2(r1);
            float2 f2 = fp8x2_to_f2(r2);
            float2 f3 = fp8x2_to_f2(r3);
            sx += (f0.x + f1.x) + (f2.x + f3.x);
            sy += (f0.y + f1.y) + (f2.y + f3.y);
        }
        for (; i + 1 < m; i += 2) {
            int s0 = __shfl_sync(0xffffffffu, srcl, i);
            int s1 = __shfl_sync(0xffffffffu, srcl, i + 1);
            float2 f0 = fp8x2_to_f2(g_h8[(size_t)s0 * 32 + lane]);
            float2 f1 = fp8x2_to_f2(g_h8[(size_t)s1 * 32 + lane]);
            sx += f0.x + f1.x;
            sy += f0.y + f1.y;
        }
        if (i < m) {
            int s0 = __shfl_sync(0xffffffffu, srcl, i);
            float2 f0 = fp8x2_to_f2(g_h8[(size_t)s0 * 32 + lane]);
            sx += f0.x;
            sy += f0.y;
        }
    }
    float2 bv = ((const float2*)b)[lane];
    float vx = bv.x + d * sx;
    float vy = bv.y + d * sy;
    if (doRelu) { vx = fmaxf(vx, 0.f); vy = fmaxf(vy, 0.f); }
    g_xb[(size_t)n * 32 + lane] = __floats2bfloat162_rn(vx, vy);
}

// ---------------------------------------------------------------------------
// k_prededge: h = relu(A[u]+B[p]+b1); out = 5*sigmoid(h.W2 + b2)
// 8 lanes per edge (4 edges/warp); uint2 row reads (8B/lane = 8 fp8 cols).
// ---------------------------------------------------------------------------
__global__ __launch_bounds__(256) void k_prededge(
    const int* __restrict__ ei,
    const float* __restrict__ b1, const float* __restrict__ W2,
    const float* __restrict__ b2, float* __restrict__ out)
{
    __shared__ float b1s[64], w2s[64];
    __shared__ float b2v;
    int tid = threadIdx.x;
    if (tid < 64) { b1s[tid] = b1[tid]; w2s[tid] = W2[tid]; }
    if (tid == 0) b2v = b2[0];
    __syncthreads();

    int e = blockIdx.x * 32 + (tid >> 3);
    if (e >= NE) return;
    int lg = tid & 7;            // 8 lanes/edge, 8 fp8 cols per lane
    int u = ei[e];
    int p = ei[NE + e];
    uint2 ar = ((const uint2*)g_h8)[(size_t)u * 8 + lg];
    uint2 br = ((const uint2*)g_h8)[(size_t)(NU + p) * 8 + lg];
    float4 b1a = ((const float4*)b1s)[lg * 2];
    float4 b1b = ((const float4*)b1s)[lg * 2 + 1];
    float4 w2a = ((const float4*)w2s)[lg * 2];
    float4 w2b = ((const float4*)w2s)[lg * 2 + 1];
    float2 a0 = fp8x2_to_f2((unsigned short)(ar.x & 0xffffu));
    float2 a1 = fp8x2_to_f2((unsigned short)(ar.x >> 16));
    float2 a2 = fp8x2_to_f2((unsigned short)(ar.y & 0xffffu));
    float2 a3 = fp8x2_to_f2((unsigned short)(ar.y >> 16));
    float2 c0 = fp8x2_to_f2((unsigned short)(br.x & 0xffffu));
    float2 c1 = fp8x2_to_f2((unsigned short)(br.x >> 16));
    float2 c2 = fp8x2_to_f2((unsigned short)(br.y & 0xffffu));
    float2 c3 = fp8x2_to_f2((unsigned short)(br.y >> 16));
    float h0 = fmaxf(a0.x + c0.x + b1a.x, 0.f);
    float h1 = fmaxf(a0.y + c0.y + b1a.y, 0.f);
    float h2 = fmaxf(a1.x + c1.x + b1a.z, 0.f);
    float h3 = fmaxf(a1.y + c1.y + b1a.w, 0.f);
    float h4 = fmaxf(a2.x + c2.x + b1b.x, 0.f);
    float h5 = fmaxf(a2.y + c2.y + b1b.y, 0.f);
    float h6 = fmaxf(a3.x + c3.x + b1b.z, 0.f);
    float h7 = fmaxf(a3.y + c3.y + b1b.w, 0.f);
    float part = (h0 * w2a.x + h1 * w2a.y + h2 * w2a.z + h3 * w2a.w)
               + (h4 * w2b.x + h5 * w2b.y + h6 * w2b.z + h7 * w2b.w);
    #pragma unroll
    for (int off = 4; off; off >>= 1)
        part += __shfl_xor_sync(0xffffffffu, part, off);
    if (lg == 0) {
        float z = part + b2v;
        out[e] = 5.f / (1.f + expf(-z));
    }
}

// ---------------------------------------------------------------------------
extern "C" void kernel_launch(void* const* d_in, const int* in_sizes, int n_in,
                              void* d_out, int out_size)
{
    const int*   ei  = (const int*)d_in[0];   // [2, NE] int32
    const float* uf  = (const float*)d_in[1];
    const float* pf  = (const float*)d_in[2];
    const float* ue  = (const float*)d_in[3];
    const float* pe  = (const float*)d_in[4];
    const float* Wuf = (const float*)d_in[5];
    const float* buf_= (const float*)d_in[6];
    const float* Wpf = (const float*)d_in[7];
    const float* bpf = (const float*)d_in[8];
    const float* c1W = (const float*)d_in[9];
    const float* c1b = (const float*)d_in[10];
    const float* c2W = (const float*)d_in[11];
    const float* c2b = (const float*)d_in[12];
    const float* pW1 = (const float*)d_in[13];
    const float* pb1 = (const float*)d_in[14];
    const float* pW2 = (const float*)d_in[15];
    const float* pb2 = (const float*)d_in[16];
    float* out = (float*)d_out;

    k_zero <<<(NN + 255) / 256, 256>>>();
    k_build<<<(NE + 255) / 256, 256>>>(ei);

    // x -> g_xb
    k_feat_t<<<GU + GP, 256>>>(uf, pf, ue, pe, Wuf, buf_, Wpf, bpf);

    // conv1: hs1 = (x @ c1W) * d -> g_h8;  xin2 = relu(c1b + d*(own+sum)) -> g_xb
    k_mm <<<GU + GP, 256>>>(c1W, c1W, 1);
    k_agg<<<NN / 8, 256>>>(c1b, 1);

    // conv2: hs2 = (xin2 @ c2W) * d -> g_h8;  xin3 = c2b + d*(own+sum) -> g_xb
    k_mm <<<GU + GP, 256>>>(c2W, c2W, 1);
    k_agg<<<NN / 8, 256>>>(c2b, 0);

    // prednode: projections = xin3 @ W1half -> g_h8
    k_mm <<<GU + GP, 256>>>(pW1, pW1 + 4096, 0);

    // per-edge combine
    k_prededge<<<NE / 32, 256>>>(ei, pb1, pW2, pb2, out);
}

// round 12
// speedup vs baseline: 1.4634x; 1.0436x over previous
#include <cuda_runtime.h>
#include <cuda_bf16.h>
#include <cuda_fp8.h>
#include <cstdint>
#include <math.h>

#define NU 200000
#define NP 100000
#define NN 300000
#define NE 1000000
#define CAP 64             // adjacency slots per node (Poisson(~6.7): overflow impossible)
#define STRIDE 72          // bf16 units, padded row stride for smem tiles
#define GU 1563            // ceil(NU/128)
#define GP 782             // ceil(NP/128)

// Scratch (module-static device memory; sanctioned by harness rules)
__device__ __nv_bfloat162 g_xb[(size_t)NN * 32];     // GEMM inputs (bf16)
__device__ unsigned short g_h8[(size_t)NN * 32];     // messages / projections (fp8x2 e4m3)
__device__ int            g_cnt[NN];
__device__ int            g_adj[(size_t)NN * CAP];

// ---------------------------------------------------------------------------
// helpers
// ---------------------------------------------------------------------------
__device__ __forceinline__ unsigned pack_bf2(float x, float y) {
    __nv_bfloat162 h = __floats2bfloat162_rn(x, y);
    return *(unsigned*)&h;
}
__device__ __forceinline__ unsigned short f2_to_fp8x2(float x, float y) {
    float2 f = make_float2(x, y);
    return (unsigned short)__nv_cvt_float2_to_fp8x2(f, __NV_SATFINITE, __NV_E4M3);
}
__device__ __forceinline__ float2 fp8x2_to_f2(unsigned short v) {
    __half2_raw hr = __nv_cvt_fp8x2_to_halfraw2((__nv_fp8x2_storage_t)v, __NV_E4M3);
    return __half22float2(*(__half2*)&hr);
}

__device__ __forceinline__ void ldmA(uint32_t addr, uint32_t& a0, uint32_t& a1,
                                     uint32_t& a2, uint32_t& a3) {
    asm volatile("ldmatrix.sync.aligned.m8n8.x4.shared.b16 {%0,%1,%2,%3},[%4];"
                 : "=r"(a0), "=r"(a1), "=r"(a2), "=r"(a3) : "r"(addr));
}
__device__ __forceinline__ void ldmBT(uint32_t addr, uint32_t& b0, uint32_t& b1,
                                      uint32_t& b2, uint32_t& b3) {
    asm volatile("ldmatrix.sync.aligned.m8n8.x4.trans.shared.b16 {%0,%1,%2,%3},[%4];"
                 : "=r"(b0), "=r"(b1), "=r"(b2), "=r"(b3) : "r"(addr));
}
__device__ __forceinline__ void mma16816(float* c, uint32_t a0, uint32_t a1,
                                         uint32_t a2, uint32_t a3,
                                         uint32_t b0, uint32_t b1) {
    asm volatile("mma.sync.aligned.m16n8k16.row.col.f32.bf16.bf16.f32 "
                 "{%0,%1,%2,%3},{%4,%5,%6,%7},{%8,%9},{%0,%1,%2,%3};"
                 : "+f"(c[0]), "+f"(c[1]), "+f"(c[2]), "+f"(c[3])
                 : "r"(a0), "r"(a1), "r"(a2), "r"(a3), "r"(b0), "r"(b1));
}

// One K=64 chunk: C[warp 16 rows x 64 cols] += xt_warp[16x64] @ wt[64x64]
__device__ __forceinline__ void mma_core(uint32_t xtw, uint32_t wtb, int l,
                                         float cf[8][4]) {
    uint32_t rowOff = (uint32_t)(((l & 7) + ((l >> 3) & 1) * 8) * STRIDE + (l >> 4) * 8) * 2;
    uint32_t aAddr = xtw + rowOff;
    uint32_t bAddr = wtb + rowOff;
    #pragma unroll
    for (int ks = 0; ks < 4; ks++) {
        uint32_t a0, a1, a2, a3;
        ldmA(aAddr + ks * 32, a0, a1, a2, a3);
        #pragma unroll
        for (int np = 0; np < 4; np++) {
            uint32_t b0, b1, b2, b3;
            ldmBT(bAddr + (uint32_t)(ks * 16 * STRIDE + np * 16) * 2, b0, b1, b2, b3);
            mma16816(cf[2 * np],     a0, a1, a2, a3, b0, b1);
            mma16816(cf[2 * np + 1], a0, a1, a2, a3, b2, b3);
        }
    }
}

// ---------------------------------------------------------------------------
// Adjacency build
// ---------------------------------------------------------------------------
__global__ void k_zero() {
    int n = blockIdx.x * blockDim.x + threadIdx.x;
    if (n < NN) g_cnt[n] = 0;
}
__global__ void k_build(const int* __restrict__ ei) {
    int e = blockIdx.x * blockDim.x + threadIdx.x;
    if (e < NE) {
        int u = ei[e];
        int p = ei[NE + e];
        int s1 = atomicAdd(&g_cnt[u], 1);
        if (s1 < CAP) g_adj[(size_t)u * CAP + s1] = p;   // message p -> u
        int s2 = atomicAdd(&g_cnt[p], 1);
        if (s2 < CAP) g_adj[(size_t)p * CAP + s2] = u;   // message u -> p
    }
}

// ---------------------------------------------------------------------------
// Feature projection (tensor core): g_xb[n] = bf16(feat[n](128) @ W + b + emb[n])
// Split grid: blocks [0,GU) users, [GU,GU+GP) products.
// ---------------------------------------------------------------------------
__global__ __launch_bounds__(256, 3) void k_feat_t(
    const float* __restrict__ uf, const float* __restrict__ pf,
    const float* __restrict__ ue, const float* __restrict__ pe,
    const float* __restrict__ Wuf, const float* __restrict__ buf_,
    const float* __restrict__ Wpf, const float* __restrict__ bpf)
{
    __shared__ __align__(16) __nv_bfloat16 xt[128 * STRIDE];
    __shared__ __align__(16) __nv_bfloat16 wt[64 * STRIDE];
    __shared__ float bs[64];

    int bid = blockIdx.x;
    bool isUser = bid < GU;
    int lrow0 = isUser ? bid * 128 : (bid - GU) * 128;
    int nloc  = isUser ? NU : NP;
    const float* feat = isUser ? uf : pf;
    const float* emb  = isUser ? ue : pe;
    const float* W    = isUser ? Wuf : Wpf;
    const float* b    = isUser ? buf_ : bpf;
    int grow0 = isUser ? lrow0 : NU + lrow0;

    int tid = threadIdx.x;
    if (tid < 32) ((float2*)bs)[tid] = ((const float2*)b)[tid];

    int l = tid & 31, w = tid >> 5;
    float cf[8][4];
    #pragma unroll
    for (int j = 0; j < 8; j++)
        #pragma unroll
        for (int q = 0; q < 4; q++) cf[j][q] = 0.f;

    const float4* W4 = (const float4*)W;
    const float4* f4 = (const float4*)feat;   // row stride 32 float4

    #pragma unroll
    for (int ch = 0; ch < 2; ch++) {
        if (ch) __syncthreads();
        #pragma unroll
        for (int i = 0; i < 4; i++) {
            int idx = tid + i * 256, r = idx >> 4, c4 = idx & 15;
            float4 v = W4[ch * 1024 + idx];
            *(uint2*)(&wt[r * STRIDE + c4 * 4]) =
                make_uint2(pack_bf2(v.x, v.y), pack_bf2(v.z, v.w));
        }
        #pragma unroll
        for (int i = 0; i < 8; i++) {
            int idx = tid + i * 256, r = idx >> 4, c4 = idx & 15;
            int lr = lrow0 + r;
            float4 v = make_float4(0.f, 0.f, 0.f, 0.f);
            if (lr < nloc) v = f4[(size_t)lr * 32 + ch * 16 + c4];
            *(uint2*)(&xt[r * STRIDE + c4 * 4]) =
                make_uint2(pack_bf2(v.x, v.y), pack_bf2(v.z, v.w));
        }
        __syncthreads();
        mma_core((uint32_t)__cvta_generic_to_shared(xt) + (uint32_t)(w * 16 * STRIDE) * 2,
                 (uint32_t)__cvta_generic_to_shared(wt), l, cf);
    }

    int rl = w * 16 + (l >> 2);
    #pragma unroll
    for (int half = 0; half < 2; half++) {
        int lr = lrow0 + rl + half * 8;
        if (lr < nloc) {
            size_t gr = (size_t)(grow0 + rl + half * 8);
            #pragma unroll
            for (int j = 0; j < 8; j++) {
                int c2 = j * 4 + (l & 3);
                float2 ev = ((const float2*)emb)[(size_t)lr * 32 + c2];
                g_xb[gr * 32 + c2] = __floats2bfloat162_rn(
                    cf[j][half * 2 + 0] + bs[c2 * 2]     + ev.x,
                    cf[j][half * 2 + 1] + bs[c2 * 2 + 1] + ev.y);
            }
        }
    }
}

// ---------------------------------------------------------------------------
// k_mm: g_h8[n] = fp8( (g_xb[n] @ W) * (epiDis ? dis[n] : 1) )
// Split grid; Wu/Wp allow per-half weights (prednode). conv: Wu==Wp.
// ---------------------------------------------------------------------------
__global__ __launch_bounds__(256) void k_mm(
    const float* __restrict__ Wu, const float* __restrict__ Wp, int epiDis)
{
    __shared__ __align__(16) __nv_bfloat16 xt[128 * STRIDE];
    __shared__ __align__(16) __nv_bfloat16 wt[64 * STRIDE];

    int bid = blockIdx.x;
    bool isUser = bid < GU;
    int lrow0 = isUser ? bid * 128 : (bid - GU) * 128;
    int nloc  = isUser ? NU : NP;
    int grow0 = isUser ? lrow0 : NU + lrow0;
    const float* W = isUser ? Wu : Wp;

    int tid = threadIdx.x;
    #pragma unroll
    for (int i = 0; i < 4; i++) {
        int idx = tid + i * 256, r = idx >> 4, c4 = idx & 15;
        float4 v = ((const float4*)W)[idx];
        *(uint2*)(&wt[r * STRIDE + c4 * 4]) =
            make_uint2(pack_bf2(v.x, v.y), pack_bf2(v.z, v.w));
    }
    const uint4* x4 = (const uint4*)g_xb;
    #pragma unroll
    for (int i = 0; i < 4; i++) {
        int idx = tid + i * 256, r = idx >> 3, c = idx & 7;
        int lr = lrow0 + r;
        uint4 v = make_uint4(0u, 0u, 0u, 0u);
        if (lr < nloc) v = x4[(size_t)(grow0 + r) * 8 + c];
        *(uint4*)(&xt[r * STRIDE + c * 8]) = v;
    }
    __syncthreads();

    int l = tid & 31, w = tid >> 5;
    float cf[8][4];
    #pragma unroll
    for (int j = 0; j < 8; j++)
        #pragma unroll
        for (int q = 0; q < 4; q++) cf[j][q] = 0.f;

    mma_core((uint32_t)__cvta_generic_to_shared(xt) + (uint32_t)(w * 16 * STRIDE) * 2,
             (uint32_t)__cvta_generic_to_shared(wt), l, cf);

    int rl = w * 16 + (l >> 2);
    #pragma unroll
    for (int half = 0; half < 2; half++) {
        int lr = lrow0 + rl + half * 8;
        if (lr < nloc) {
            int gr = grow0 + rl + half * 8;
            float d = epiDis ? rsqrtf((float)(g_cnt[gr] + 1)) : 1.f;
            #pragma unroll
            for (int j = 0; j < 8; j++) {
                int c2 = j * 4 + (l & 3);
                g_h8[(size_t)gr * 32 + c2] = f2_to_fp8x2(
                    cf[j][half * 2 + 0] * d, cf[j][half * 2 + 1] * d);
            }
        }
    }
}

// ---------------------------------------------------------------------------
// k_agg: g_xb[n] = act( b + dis[n] * (g_h8[n] + sum_{src in adj[n]} g_h8[src]) )
// HALF-warp per node (fp8 rows are 64B = 16 lanes x 4B); 2 nodes per warp.
// ---------------------------------------------------------------------------
__global__ __launch_bounds__(256) void k_agg(const float* __restrict__ b,
                                             int doRelu)
{
    int n = blockIdx.x * 16 + (threadIdx.x >> 4);
    if (n >= NN) return;
    int lane = threadIdx.x & 15;          // 4 fp8 cols pairs => cols [4l,4l+4)
    int c = g_cnt[n];
    if (c > CAP) c = CAP;
    float d = rsqrtf((float)(c + 1));
    const unsigned* h32 = (const unsigned*)g_h8;   // 4B = 4 fp8 values
    unsigned own = h32[(size_t)n * 16 + lane];
    float2 sA = fp8x2_to_f2((unsigned short)(own & 0xffffu));
    float2 sB = fp8x2_to_f2((unsigned short)(own >> 16));
    size_t base = (size_t)n * CAP;
    for (int i0 = 0; i0 < c; i0 += 16) {
        int m = min(16, c - i0);
        int srcl = (lane < m) ? g_adj[base + i0 + lane] : 0;
        int i = 0;
        for (; i + 3 < m; i += 4) {
            int s0 = __shfl_sync(0xffffffffu, srcl, i,     16);
            int s1 = __shfl_sync(0xffffffffu, srcl, i + 1, 16);
            int s2 = __shfl_sync(0xffffffffu, srcl, i + 2, 16);
            int s3 = __shfl_sync(0xffffffffu, srcl, i + 3, 16);
            unsigned r0 = h32[(size_t)s0 * 16 + lane];
            unsigned r1 = h32[(size_t)s1 * 16 + lane];
            unsigned r2 = h32[(size_t)s2 * 16 + lane];
            unsigned r3 = h32[(size_t)s3 * 16 + lane];
            float2 a0 = fp8x2_to_f2((unsigned short)(r0 & 0xffffu));
            float2 b0 = fp8x2_to_f2((unsigned short)(r0 >> 16));
            float2 a1 = fp8x2_to_f2((unsigned short)(r1 & 0xffffu));
            float2 b1 = fp8x2_to_f2((unsigned short)(r1 >> 16));
            float2 a2 = fp8x2_to_f2((unsigned short)(r2 & 0xffffu));
            float2 b2 = fp8x2_to_f2((unsigned short)(r2 >> 16));
            float2 a3 = fp8x2_to_f2((unsigned short)(r3 & 0xffffu));
            float2 b3 = fp8x2_to_f2((unsigned short)(r3 >> 16));
            sA.x += (a0.x + a1.x) + (a2.x + a3.x);
            sA.y += (a0.y + a1.y) + (a2.y + a3.y);
            sB.x += (b0.x + b1.x) + (b2.x + b3.x);
            sB.y += (b0.y + b1.y) + (b2.y + b3.y);
        }
        for (; i < m; i++) {
            int s0 = __shfl_sync(0xffffffffu, srcl, i, 16);
            unsigned r0 = h32[(size_t)s0 * 16 + lane];
            float2 a0 = fp8x2_to_f2((unsigned short)(r0 & 0xffffu));
            float2 b0 = fp8x2_to_f2((unsigned short)(r0 >> 16));
            sA.x += a0.x; sA.y += a0.y;
            sB.x += b0.x; sB.y += b0.y;
        }
    }
    float4 bv = ((const float4*)b)[lane];
    float v0 = bv.x + d * sA.x;
    float v1 = bv.y + d * sA.y;
    float v2 = bv.z + d * sB.x;
    float v3 = bv.w + d * sB.y;
    if (doRelu) {
        v0 = fmaxf(v0, 0.f); v1 = fmaxf(v1, 0.f);
        v2 = fmaxf(v2, 0.f); v3 = fmaxf(v3, 0.f);
    }
    ((uint2*)g_xb)[(size_t)n * 16 + lane] =
        make_uint2(pack_bf2(v0, v1), pack_bf2(v2, v3));
}

// ---------------------------------------------------------------------------
// k_prededge: h = relu(A[u]+B[p]+b1); out = 5*sigmoid(h.W2 + b2)
// 8 lanes per edge (4 edges/warp); uint2 row reads (8B/lane = 8 fp8 cols).
// ---------------------------------------------------------------------------
__global__ __launch_bounds__(256) void k_prededge(
    const int* __restrict__ ei,
    const float* __restrict__ b1, const float* __restrict__ W2,
    const float* __restrict__ b2, float* __restrict__ out)
{
    __shared__ float b1s[64], w2s[64];
    __shared__ float b2v;
    int tid = threadIdx.x;
    if (tid < 64) { b1s[tid] = b1[tid]; w2s[tid] = W2[tid]; }
    if (tid == 0) b2v = b2[0];
    __syncthreads();

    int e = blockIdx.x * 32 + (tid >> 3);
    if (e >= NE) return;
    int lg = tid & 7;            // 8 lanes/edge, 8 fp8 cols per lane
    int u = ei[e];
    int p = ei[NE + e];
    uint2 ar = ((const uint2*)g_h8)[(size_t)u * 8 + lg];
    uint2 br = ((const uint2*)g_h8)[(size_t)(NU + p) * 8 + lg];
    float4 b1a = ((const float4*)b1s)[lg * 2];
    float4 b1b = ((const float4*)b1s)[lg * 2 + 1];
    float4 w2a = ((const float4*)w2s)[lg * 2];
    float4 w2b = ((const float4*)w2s)[lg * 2 + 1];
    float2 a0 = fp8x2_to_f2((unsigned short)(ar.x & 0xffffu));
    float2 a1 = fp8x2_to_f2((unsigned short)(ar.x >> 16));
    float2 a2 = fp8x2_to_f2((unsigned short)(ar.y & 0xffffu));
    float2 a3 = fp8x2_to_f2((unsigned short)(ar.y >> 16));
    float2 c0 = fp8x2_to_f2((unsigned short)(br.x & 0xffffu));
    float2 c1 = fp8x2_to_f2((unsigned short)(br.x >> 16));
    float2 c2 = fp8x2_to_f2((unsigned short)(br.y & 0xffffu));
    float2 c3 = fp8x2_to_f2((unsigned short)(br.y >> 16));
    float h0 = fmaxf(a0.x + c0.x + b1a.x, 0.f);
    float h1 = fmaxf(a0.y + c0.y + b1a.y, 0.f);
    float h2 = fmaxf(a1.x + c1.x + b1a.z, 0.f);
    float h3 = fmaxf(a1.y + c1.y + b1a.w, 0.f);
    float h4 = fmaxf(a2.x + c2.x + b1b.x, 0.f);
    float h5 = fmaxf(a2.y + c2.y + b1b.y, 0.f);
    float h6 = fmaxf(a3.x + c3.x + b1b.z, 0.f);
    float h7 = fmaxf(a3.y + c3.y + b1b.w, 0.f);
    float part = (h0 * w2a.x + h1 * w2a.y + h2 * w2a.z + h3 * w2a.w)
               + (h4 * w2b.x + h5 * w2b.y + h6 * w2b.z + h7 * w2b.w);
    #pragma unroll
    for (int off = 4; off; off >>= 1)
        part += __shfl_xor_sync(0xffffffffu, part, off);
    if (lg == 0) {
        float z = part + b2v;
        out[e] = 5.f / (1.f + expf(-z));
    }
}

// ---------------------------------------------------------------------------
extern "C" void kernel_launch(void* const* d_in, const int* in_sizes, int n_in,
                              void* d_out, int out_size)
{
    const int*   ei  = (const int*)d_in[0];   // [2, NE] int32
    const float* uf  = (const float*)d_in[1];
    const float* pf  = (const float*)d_in[2];
    const float* ue  = (const float*)d_in[3];
    const float* pe  = (const float*)d_in[4];
    const float* Wuf = (const float*)d_in[5];
    const float* buf_= (const float*)d_in[6];
    const float* Wpf = (const float*)d_in[7];
    const float* bpf = (const float*)d_in[8];
    const float* c1W = (const float*)d_in[9];
    const float* c1b = (const float*)d_in[10];
    const float* c2W = (const float*)d_in[11];
    const float* c2b = (const float*)d_in[12];
    const float* pW1 = (const float*)d_in[13];
    const float* pb1 = (const float*)d_in[14];
    const float* pW2 = (const float*)d_in[15];
    const float* pb2 = (const float*)d_in[16];
    float* out = (float*)d_out;

    // Fork the capture: adjacency build (s2) runs concurrently with feat (main).
    // Streams/events are intentionally never destroyed (destroying a stream
    // participating in capture would invalidate it); host-side leak of a few
    // objects across the harness's handful of kernel_launch calls is benign.
    cudaStream_t s2 = 0;
    cudaEvent_t evFork = 0, evJoin = 0;
    bool par = (cudaStreamCreateWithFlags(&s2, cudaStreamNonBlocking) == cudaSuccess) &&
               (cudaEventCreateWithFlags(&evFork, cudaEventDisableTiming) == cudaSuccess) &&
               (cudaEventCreateWithFlags(&evJoin, cudaEventDisableTiming) == cudaSuccess);

    if (par) {
        cudaEventRecord(evFork, 0);
        cudaStreamWaitEvent(s2, evFork, 0);
        k_zero <<<(NN + 255) / 256, 256, 0, s2>>>();
        k_build<<<(NE + 255) / 256, 256, 0, s2>>>(ei);
        cudaEventRecord(evJoin, s2);
        k_feat_t<<<GU + GP, 256>>>(uf, pf, ue, pe, Wuf, buf_, Wpf, bpf);
        cudaStreamWaitEvent(0, evJoin, 0);
    } else {
        k_zero <<<(NN + 255) / 256, 256>>>();
        k_build<<<(NE + 255) / 256, 256>>>(ei);
        k_feat_t<<<GU + GP, 256>>>(uf, pf, ue, pe, Wuf, buf_, Wpf, bpf);
    }

    // conv1: hs1 = (x @ c1W) * d -> g_h8;  xin2 = relu(c1b + d*(own+sum)) -> g_xb
    k_mm <<<GU + GP, 256>>>(c1W, c1W, 1);
    k_agg<<<NN / 16, 256>>>(c1b, 1);

    // conv2: hs2 = (xin2 @ c2W) * d -> g_h8;  xin3 = c2b + d*(own+sum) -> g_xb
    k_mm <<<GU + GP, 256>>>(c2W, c2W, 1);
    k_agg<<<NN / 16, 256>>>(c2b, 0);

    // prednode: projections = xin3 @ W1half -> g_h8
    k_mm <<<GU + GP, 256>>>(pW1, pW1 + 4096, 0);

    // per-edge combine
    k_prededge<<<NE / 32, 256>>>(ei, pb1, pW2, pb2, out);
}

// round 13
// speedup vs baseline: 1.4789x; 1.0106x over previous
#include <cuda_runtime.h>
#include <cuda_bf16.h>
#include <cuda_fp8.h>
#include <cstdint>
#include <math.h>

#define NU 200000
#define NP 100000
#define NN 300000
#define NE 1000000
#define CAP 64             // adjacency slots per node (Poisson(~6.7): overflow impossible)
#define STRIDE 72          // bf16 units, padded row stride for smem tiles
#define GU 1563            // ceil(NU/128)
#define GP 782             // ceil(NP/128)

// Scratch (module-static device memory; sanctioned by harness rules)
__device__ __nv_bfloat162 g_xb[(size_t)NN * 32];     // GEMM inputs (bf16)
__device__ unsigned short g_h8[(size_t)NN * 32];     // messages / projections (fp8x2 e4m3)
__device__ int            g_cnt[NN];
__device__ int            g_adj[(size_t)NN * CAP];

// ---------------------------------------------------------------------------
// helpers
// ---------------------------------------------------------------------------
__device__ __forceinline__ unsigned pack_bf2(float x, float y) {
    __nv_bfloat162 h = __floats2bfloat162_rn(x, y);
    return *(unsigned*)&h;
}
__device__ __forceinline__ unsigned short f2_to_fp8x2(float x, float y) {
    float2 f = make_float2(x, y);
    return (unsigned short)__nv_cvt_float2_to_fp8x2(f, __NV_SATFINITE, __NV_E4M3);
}
__device__ __forceinline__ float2 fp8x2_to_f2(unsigned short v) {
    __half2_raw hr = __nv_cvt_fp8x2_to_halfraw2((__nv_fp8x2_storage_t)v, __NV_E4M3);
    return __half22float2(*(__half2*)&hr);
}

__device__ __forceinline__ void ldmA(uint32_t addr, uint32_t& a0, uint32_t& a1,
                                     uint32_t& a2, uint32_t& a3) {
    asm volatile("ldmatrix.sync.aligned.m8n8.x4.shared.b16 {%0,%1,%2,%3},[%4];"
                 : "=r"(a0), "=r"(a1), "=r"(a2), "=r"(a3) : "r"(addr));
}
__device__ __forceinline__ void ldmBT(uint32_t addr, uint32_t& b0, uint32_t& b1,
                                      uint32_t& b2, uint32_t& b3) {
    asm volatile("ldmatrix.sync.aligned.m8n8.x4.trans.shared.b16 {%0,%1,%2,%3},[%4];"
                 : "=r"(b0), "=r"(b1), "=r"(b2), "=r"(b3) : "r"(addr));
}
__device__ __forceinline__ void mma16816(float* c, uint32_t a0, uint32_t a1,
                                         uint32_t a2, uint32_t a3,
                                         uint32_t b0, uint32_t b1) {
    asm volatile("mma.sync.aligned.m16n8k16.row.col.f32.bf16.bf16.f32 "
                 "{%0,%1,%2,%3},{%4,%5,%6,%7},{%8,%9},{%0,%1,%2,%3};"
                 : "+f"(c[0]), "+f"(c[1]), "+f"(c[2]), "+f"(c[3])
                 : "r"(a0), "r"(a1), "r"(a2), "r"(a3), "r"(b0), "r"(b1));
}

// One K=64 chunk: C[warp 16 rows x 64 cols] += xt_warp[16x64] @ wt[64x64]
__device__ __forceinline__ void mma_core(uint32_t xtw, uint32_t wtb, int l,
                                         float cf[8][4]) {
    uint32_t rowOff = (uint32_t)(((l & 7) + ((l >> 3) & 1) * 8) * STRIDE + (l >> 4) * 8) * 2;
    uint32_t aAddr = xtw + rowOff;
    uint32_t bAddr = wtb + rowOff;
    #pragma unroll
    for (int ks = 0; ks < 4; ks++) {
        uint32_t a0, a1, a2, a3;
        ldmA(aAddr + ks * 32, a0, a1, a2, a3);
        #pragma unroll
        for (int np = 0; np < 4; np++) {
            uint32_t b0, b1, b2, b3;
            ldmBT(bAddr + (uint32_t)(ks * 16 * STRIDE + np * 16) * 2, b0, b1, b2, b3);
            mma16816(cf[2 * np],     a0, a1, a2, a3, b0, b1);
            mma16816(cf[2 * np + 1], a0, a1, a2, a3, b2, b3);
        }
    }
}

// ---------------------------------------------------------------------------
// Adjacency build
// ---------------------------------------------------------------------------
__global__ void k_zero() {
    int n = blockIdx.x * blockDim.x + threadIdx.x;
    if (n < NN) g_cnt[n] = 0;
}
__global__ void k_build(const int* __restrict__ ei) {
    int e = blockIdx.x * blockDim.x + threadIdx.x;
    if (e < NE) {
        int u = ei[e];
        int p = ei[NE + e];
        int s1 = atomicAdd(&g_cnt[u], 1);
        if (s1 < CAP) g_adj[(size_t)u * CAP + s1] = p;   // message p -> u
        int s2 = atomicAdd(&g_cnt[p], 1);
        if (s2 < CAP) g_adj[(size_t)p * CAP + s2] = u;   // message u -> p
    }
}

// ---------------------------------------------------------------------------
// Feature projection (tensor core): g_xb[n] = bf16(feat[n](128) @ W + b + emb[n])
// bid = blockIdx.x + bidOff; [0,GU) users, [GU,GU+GP) products.
// ---------------------------------------------------------------------------
__global__ __launch_bounds__(256, 3) void k_feat_t(
    const float* __restrict__ uf, const float* __restrict__ pf,
    const float* __restrict__ ue, const float* __restrict__ pe,
    const float* __restrict__ Wuf, const float* __restrict__ buf_,
    const float* __restrict__ Wpf, const float* __restrict__ bpf,
    int bidOff)
{
    __shared__ __align__(16) __nv_bfloat16 xt[128 * STRIDE];
    __shared__ __align__(16) __nv_bfloat16 wt[64 * STRIDE];
    __shared__ float bs[64];

    int bid = blockIdx.x + bidOff;
    bool isUser = bid < GU;
    int lrow0 = isUser ? bid * 128 : (bid - GU) * 128;
    int nloc  = isUser ? NU : NP;
    const float* feat = isUser ? uf : pf;
    const float* emb  = isUser ? ue : pe;
    const float* W    = isUser ? Wuf : Wpf;
    const float* b    = isUser ? buf_ : bpf;
    int grow0 = isUser ? lrow0 : NU + lrow0;

    int tid = threadIdx.x;
    if (tid < 32) ((float2*)bs)[tid] = ((const float2*)b)[tid];

    int l = tid & 31, w = tid >> 5;
    float cf[8][4];
    #pragma unroll
    for (int j = 0; j < 8; j++)
        #pragma unroll
        for (int q = 0; q < 4; q++) cf[j][q] = 0.f;

    const float4* W4 = (const float4*)W;
    const float4* f4 = (const float4*)feat;   // row stride 32 float4

    #pragma unroll
    for (int ch = 0; ch < 2; ch++) {
        if (ch) __syncthreads();
        #pragma unroll
        for (int i = 0; i < 4; i++) {
            int idx = tid + i * 256, r = idx >> 4, c4 = idx & 15;
            float4 v = W4[ch * 1024 + idx];
            *(uint2*)(&wt[r * STRIDE + c4 * 4]) =
                make_uint2(pack_bf2(v.x, v.y), pack_bf2(v.z, v.w));
        }
        #pragma unroll
        for (int i = 0; i < 8; i++) {
            int idx = tid + i * 256, r = idx >> 4, c4 = idx & 15;
            int lr = lrow0 + r;
            float4 v = make_float4(0.f, 0.f, 0.f, 0.f);
            if (lr < nloc) v = f4[(size_t)lr * 32 + ch * 16 + c4];
            *(uint2*)(&xt[r * STRIDE + c4 * 4]) =
                make_uint2(pack_bf2(v.x, v.y), pack_bf2(v.z, v.w));
        }
        __syncthreads();
        mma_core((uint32_t)__cvta_generic_to_shared(xt) + (uint32_t)(w * 16 * STRIDE) * 2,
                 (uint32_t)__cvta_generic_to_shared(wt), l, cf);
    }

    int rl = w * 16 + (l >> 2);
    #pragma unroll
    for (int half = 0; half < 2; half++) {
        int lr = lrow0 + rl + half * 8;
        if (lr < nloc) {
            size_t gr = (size_t)(grow0 + rl + half * 8);
            #pragma unroll
            for (int j = 0; j < 8; j++) {
                int c2 = j * 4 + (l & 3);
                float2 ev = ((const float2*)emb)[(size_t)lr * 32 + c2];
                g_xb[gr * 32 + c2] = __floats2bfloat162_rn(
                    cf[j][half * 2 + 0] + bs[c2 * 2]     + ev.x,
                    cf[j][half * 2 + 1] + bs[c2 * 2 + 1] + ev.y);
            }
        }
    }
}

// ---------------------------------------------------------------------------
// k_mm: g_h8[n] = fp8( (g_xb[n] @ W) * (epiDis ? dis[n] : 1) )
// bid = blockIdx.x + bidOff; Wu/Wp allow per-half weights (prednode).
// ---------------------------------------------------------------------------
__global__ __launch_bounds__(256) void k_mm(
    const float* __restrict__ Wu, const float* __restrict__ Wp, int epiDis,
    int bidOff)
{
    __shared__ __align__(16) __nv_bfloat16 xt[128 * STRIDE];
    __shared__ __align__(16) __nv_bfloat16 wt[64 * STRIDE];

    int bid = blockIdx.x + bidOff;
    bool isUser = bid < GU;
    int lrow0 = isUser ? bid * 128 : (bid - GU) * 128;
    int nloc  = isUser ? NU : NP;
    int grow0 = isUser ? lrow0 : NU + lrow0;
    const float* W = isUser ? Wu : Wp;

    int tid = threadIdx.x;
    #pragma unroll
    for (int i = 0; i < 4; i++) {
        int idx = tid + i * 256, r = idx >> 4, c4 = idx & 15;
        float4 v = ((const float4*)W)[idx];
        *(uint2*)(&wt[r * STRIDE + c4 * 4]) =
            make_uint2(pack_bf2(v.x, v.y), pack_bf2(v.z, v.w));
    }
    const uint4* x4 = (const uint4*)g_xb;
    #pragma unroll
    for (int i = 0; i < 4; i++) {
        int idx = tid + i * 256, r = idx >> 3, c = idx & 7;
        int lr = lrow0 + r;
        uint4 v = make_uint4(0u, 0u, 0u, 0u);
        if (lr < nloc) v = x4[(size_t)(grow0 + r) * 8 + c];
        *(uint4*)(&xt[r * STRIDE + c * 8]) = v;
    }
    __syncthreads();

    int l = tid & 31, w = tid >> 5;
    float cf[8][4];
    #pragma unroll
    for (int j = 0; j < 8; j++)
        #pragma unroll
        for (int q = 0; q < 4; q++) cf[j][q] = 0.f;

    mma_core((uint32_t)__cvta_generic_to_shared(xt) + (uint32_t)(w * 16 * STRIDE) * 2,
             (uint32_t)__cvta_generic_to_shared(wt), l, cf);

    int rl = w * 16 + (l >> 2);
    #pragma unroll
    for (int half = 0; half < 2; half++) {
        int lr = lrow0 + rl + half * 8;
        if (lr < nloc) {
            int gr = grow0 + rl + half * 8;
            float d = epiDis ? rsqrtf((float)(g_cnt[gr] + 1)) : 1.f;
            #pragma unroll
            for (int j = 0; j < 8; j++) {
                int c2 = j * 4 + (l & 3);
                g_h8[(size_t)gr * 32 + c2] = f2_to_fp8x2(
                    cf[j][half * 2 + 0] * d, cf[j][half * 2 + 1] * d);
            }
        }
    }
}

// ---------------------------------------------------------------------------
// k_agg: g_xb[n] = act( b + dis[n] * (g_h8[n] + sum_{src in adj[n]} g_h8[src]) )
// HALF-warp per node (fp8 rows are 64B = 16 lanes x 4B); node range split.
// ---------------------------------------------------------------------------
__global__ __launch_bounds__(256) void k_agg(const float* __restrict__ b,
                                             int doRelu, int nodeBase, int nNodes)
{
    int ln = blockIdx.x * 16 + (threadIdx.x >> 4);
    if (ln >= nNodes) return;
    int n = nodeBase + ln;
    int lane = threadIdx.x & 15;          // 4 fp8 cols pairs => cols [4l,4l+4)
    int c = g_cnt[n];
    if (c > CAP) c = CAP;
    float d = rsqrtf((float)(c + 1));
    const unsigned* h32 = (const unsigned*)g_h8;   // 4B = 4 fp8 values
    unsigned own = h32[(size_t)n * 16 + lane];
    float2 sA = fp8x2_to_f2((unsigned short)(own & 0xffffu));
    float2 sB = fp8x2_to_f2((unsigned short)(own >> 16));
    size_t base = (size_t)n * CAP;
    for (int i0 = 0; i0 < c; i0 += 16) {
        int m = min(16, c - i0);
        int srcl = (lane < m) ? g_adj[base + i0 + lane] : 0;
        int i = 0;
        for (; i + 3 < m; i += 4) {
            int s0 = __shfl_sync(0xffffffffu, srcl, i,     16);
            int s1 = __shfl_sync(0xffffffffu, srcl, i + 1, 16);
            int s2 = __shfl_sync(0xffffffffu, srcl, i + 2, 16);
            int s3 = __shfl_sync(0xffffffffu, srcl, i + 3, 16);
            unsigned r0 = h32[(size_t)s0 * 16 + lane];
            unsigned r1 = h32[(size_t)s1 * 16 + lane];
            unsigned r2 = h32[(size_t)s2 * 16 + lane];
            unsigned r3 = h32[(size_t)s3 * 16 + lane];
            float2 a0 = fp8x2_to_f2((unsigned short)(r0 & 0xffffu));
            float2 b0 = fp8x2_to_f2((unsigned short)(r0 >> 16));
            float2 a1 = fp8x2_to_f2((unsigned short)(r1 & 0xffffu));
            float2 b1 = fp8x2_to_f2((unsigned short)(r1 >> 16));
            float2 a2 = fp8x2_to_f2((unsigned short)(r2 & 0xffffu));
            float2 b2 = fp8x2_to_f2((unsigned short)(r2 >> 16));
            float2 a3 = fp8x2_to_f2((unsigned short)(r3 & 0xffffu));
            float2 b3 = fp8x2_to_f2((unsigned short)(r3 >> 16));
            sA.x += (a0.x + a1.x) + (a2.x + a3.x);
            sA.y += (a0.y + a1.y) + (a2.y + a3.y);
            sB.x += (b0.x + b1.x) + (b2.x + b3.x);
            sB.y += (b0.y + b1.y) + (b2.y + b3.y);
        }
        for (; i < m; i++) {
            int s0 = __shfl_sync(0xffffffffu, srcl, i, 16);
            unsigned r0 = h32[(size_t)s0 * 16 + lane];
            float2 a0 = fp8x2_to_f2((unsigned short)(r0 & 0xffffu));
            float2 b0 = fp8x2_to_f2((unsigned short)(r0 >> 16));
            sA.x += a0.x; sA.y += a0.y;
            sB.x += b0.x; sB.y += b0.y;
        }
    }
    float4 bv = ((const float4*)b)[lane];
    float v0 = bv.x + d * sA.x;
    float v1 = bv.y + d * sA.y;
    float v2 = bv.z + d * sB.x;
    float v3 = bv.w + d * sB.y;
    if (doRelu) {
        v0 = fmaxf(v0, 0.f); v1 = fmaxf(v1, 0.f);
        v2 = fmaxf(v2, 0.f); v3 = fmaxf(v3, 0.f);
    }
    ((uint2*)g_xb)[(size_t)n * 16 + lane] =
        make_uint2(pack_bf2(v0, v1), pack_bf2(v2, v3));
}

// ---------------------------------------------------------------------------
// k_prededge: h = relu(A[u]+B[p]+b1); out = 5*sigmoid(h.W2 + b2)
// 8 lanes per edge (4 edges/warp); uint2 row reads (8B/lane = 8 fp8 cols).
// ---------------------------------------------------------------------------
__global__ __launch_bounds__(256) void k_prededge(
    const int* __restrict__ ei,
    const float* __restrict__ b1, const float* __restrict__ W2,
    const float* __restrict__ b2, float* __restrict__ out)
{
    __shared__ float b1s[64], w2s[64];
    __shared__ float b2v;
    int tid = threadIdx.x;
    if (tid < 64) { b1s[tid] = b1[tid]; w2s[tid] = W2[tid]; }
    if (tid == 0) b2v = b2[0];
    __syncthreads();

    int e = blockIdx.x * 32 + (tid >> 3);
    if (e >= NE) return;
    int lg = tid & 7;            // 8 lanes/edge, 8 fp8 cols per lane
    int u = ei[e];
    int p = ei[NE + e];
    uint2 ar = ((const uint2*)g_h8)[(size_t)u * 8 + lg];
    uint2 br = ((const uint2*)g_h8)[(size_t)(NU + p) * 8 + lg];
    float4 b1a = ((const float4*)b1s)[lg * 2];
    float4 b1b = ((const float4*)b1s)[lg * 2 + 1];
    float4 w2a = ((const float4*)w2s)[lg * 2];
    float4 w2b = ((const float4*)w2s)[lg * 2 + 1];
    float2 a0 = fp8x2_to_f2((unsigned short)(ar.x & 0xffffu));
    float2 a1 = fp8x2_to_f2((unsigned short)(ar.x >> 16));
    float2 a2 = fp8x2_to_f2((unsigned short)(ar.y & 0xffffu));
    float2 a3 = fp8x2_to_f2((unsigned short)(ar.y >> 16));
    float2 c0 = fp8x2_to_f2((unsigned short)(br.x & 0xffffu));
    float2 c1 = fp8x2_to_f2((unsigned short)(br.x >> 16));
    float2 c2 = fp8x2_to_f2((unsigned short)(br.y & 0xffffu));
    float2 c3 = fp8x2_to_f2((unsigned short)(br.y >> 16));
    float h0 = fmaxf(a0.x + c0.x + b1a.x, 0.f);
    float h1 = fmaxf(a0.y + c0.y + b1a.y, 0.f);
    float h2 = fmaxf(a1.x + c1.x + b1a.z, 0.f);
    float h3 = fmaxf(a1.y + c1.y + b1a.w, 0.f);
    float h4 = fmaxf(a2.x + c2.x + b1b.x, 0.f);
    float h5 = fmaxf(a2.y + c2.y + b1b.y, 0.f);
    float h6 = fmaxf(a3.x + c3.x + b1b.z, 0.f);
    float h7 = fmaxf(a3.y + c3.y + b1b.w, 0.f);
    float part = (h0 * w2a.x + h1 * w2a.y + h2 * w2a.z + h3 * w2a.w)
               + (h4 * w2b.x + h5 * w2b.y + h6 * w2b.z + h7 * w2b.w);
    #pragma unroll
    for (int off = 4; off; off >>= 1)
        part += __shfl_xor_sync(0xffffffffu, part, off);
    if (lg == 0) {
        float z = part + b2v;
        out[e] = 5.f / (1.f + expf(-z));
    }
}

// ---------------------------------------------------------------------------
extern "C" void kernel_launch(void* const* d_in, const int* in_sizes, int n_in,
                              void* d_out, int out_size)
{
    const int*   ei  = (const int*)d_in[0];   // [2, NE] int32
    const float* uf  = (const float*)d_in[1];
    const float* pf  = (const float*)d_in[2];
    const float* ue  = (const float*)d_in[3];
    const float* pe  = (const float*)d_in[4];
    const float* Wuf = (const float*)d_in[5];
    const float* buf_= (const float*)d_in[6];
    const float* Wpf = (const float*)d_in[7];
    const float* bpf = (const float*)d_in[8];
    const float* c1W = (const float*)d_in[9];
    const float* c1b = (const float*)d_in[10];
    const float* c2W = (const float*)d_in[11];
    const float* c2b = (const float*)d_in[12];
    const float* pW1 = (const float*)d_in[13];
    const float* pb1 = (const float*)d_in[14];
    const float* pW2 = (const float*)d_in[15];
    const float* pb2 = (const float*)d_in[16];
    float* out = (float*)d_out;

    const int AGU = NU / 16;   // agg blocks users (200000/16)
    const int AGP = NP / 16;   // agg blocks products

    // Two-stream pipeline. Streams/events are created per call and leaked
    // intentionally (destroying objects used in an active capture invalidates
    // it; a handful of host objects per harness call is benign).
    cudaStream_t s2 = 0;
    cudaEvent_t ev[8] = {};
    bool par = (cudaStreamCreateWithFlags(&s2, cudaStreamNonBlocking) == cudaSuccess);
    for (int i = 0; par && i < 8; i++)
        par = (cudaEventCreateWithFlags(&ev[i], cudaEventDisableTiming) == cudaSuccess);

    if (par) {
        // fork
        cudaEventRecord(ev[0], 0);
        cudaStreamWaitEvent(s2, ev[0], 0);

        // B: adjacency; A: user features (independent)
        k_zero <<<(NN + 255) / 256, 256, 0, s2>>>();
        k_build<<<(NE + 255) / 256, 256, 0, s2>>>(ei);
        cudaEventRecord(ev[1], s2);                         // build done
        k_feat_t<<<GU, 256>>>(uf, pf, ue, pe, Wuf, buf_, Wpf, bpf, 0);
        k_feat_t<<<GP, 256, 0, s2>>>(uf, pf, ue, pe, Wuf, buf_, Wpf, bpf, GU);

        // mm1 halves (users on A needs build's g_cnt)
        cudaStreamWaitEvent(0, ev[1], 0);
        k_mm<<<GU, 256>>>(c1W, c1W, 1, 0);
        cudaEventRecord(ev[2], 0);                          // mm1_u done
        k_mm<<<GP, 256, 0, s2>>>(c1W, c1W, 1, GU);
        cudaEventRecord(ev[3], s2);                         // mm1_p done

        // agg1 halves (each needs BOTH mm1 halves) -> mm2 halves (own half only)
        cudaStreamWaitEvent(0, ev[3], 0);
        k_agg<<<AGU, 256>>>(c1b, 1, 0, NU);
        k_mm <<<GU, 256>>>(c2W, c2W, 1, 0);
        cudaEventRecord(ev[4], 0);                          // mm2_u done
        cudaStreamWaitEvent(s2, ev[2], 0);
        k_agg<<<AGP, 256, 0, s2>>>(c1b, 1, NU, NP);
        k_mm <<<GP, 256, 0, s2>>>(c2W, c2W, 1, GU);
        cudaEventRecord(ev[5], s2);                         // mm2_p done

        // agg2 halves -> mm3 (prednode) halves
        cudaStreamWaitEvent(0, ev[5], 0);
        k_agg<<<AGU, 256>>>(c2b, 0, 0, NU);
        k_mm <<<GU, 256>>>(pW1, pW1 + 4096, 0, 0);
        cudaStreamWaitEvent(s2, ev[4], 0);
        k_agg<<<AGP, 256, 0, s2>>>(c2b, 0, NU, NP);
        k_mm <<<GP, 256, 0, s2>>>(pW1, pW1 + 4096, 0, GU);
        cudaEventRecord(ev[6], s2);                         // mm3_p done (B's last)

        // prededge needs both mm3 halves
        cudaStreamWaitEvent(0, ev[6], 0);
        k_prededge<<<NE / 32, 256>>>(ei, pb1, pW2, pb2, out);
    } else {
        k_zero <<<(NN + 255) / 256, 256>>>();
        k_build<<<(NE + 255) / 256, 256>>>(ei);
        k_feat_t<<<GU + GP, 256>>>(uf, pf, ue, pe, Wuf, buf_, Wpf, bpf, 0);
        k_mm <<<GU + GP, 256>>>(c1W, c1W, 1, 0);
        k_agg<<<NN / 16, 256>>>(c1b, 1, 0, NN);
        k_mm <<<GU + GP, 256>>>(c2W, c2W, 1, 0);
        k_agg<<<NN / 16, 256>>>(c2b, 0, 0, NN);
        k_mm <<<GU + GP, 256>>>(pW1, pW1 + 4096, 0, 0);
        k_prededge<<<NE / 32, 256>>>(ei, pb1, pW2, pb2, out);
    }
}

// round 14
// speedup vs baseline: 1.5179x; 1.0263x over previous
#include <cuda_runtime.h>
#include <cuda_bf16.h>
#include <cuda_fp8.h>
#include <cstdint>
#include <math.h>

#define NU 200000
#define NP 100000
#define NN 300000
#define NE 1000000
#define CAP 64             // adjacency slots per node (Poisson(~6.7): overflow impossible)
#define STRIDE 72          // bf16 units, padded row stride for 64-col smem tiles
#define XSTR 136           // bf16 units, padded row stride for 128-col feat tile
#define GU 1563            // ceil(NU/128)
#define GP 782             // ceil(NP/128)
#define GU2 782            // ceil(NU/256)  (mm: 256 rows/block)
#define GP2 391            // ceil(NP/256)

// Scratch (module-static device memory; sanctioned by harness rules)
__device__ __nv_bfloat162 g_xb[(size_t)NN * 32];     // GEMM inputs (bf16)
__device__ unsigned short g_h8[(size_t)NN * 32];     // messages / projections (fp8x2 e4m3)
__device__ int            g_cnt[NN];
__device__ int            g_adj[(size_t)NN * CAP];

// ---------------------------------------------------------------------------
// helpers
// ---------------------------------------------------------------------------
__device__ __forceinline__ unsigned pack_bf2(float x, float y) {
    __nv_bfloat162 h = __floats2bfloat162_rn(x, y);
    return *(unsigned*)&h;
}
__device__ __forceinline__ unsigned short f2_to_fp8x2(float x, float y) {
    float2 f = make_float2(x, y);
    return (unsigned short)__nv_cvt_float2_to_fp8x2(f, __NV_SATFINITE, __NV_E4M3);
}
__device__ __forceinline__ float2 fp8x2_to_f2(unsigned short v) {
    __half2_raw hr = __nv_cvt_fp8x2_to_halfraw2((__nv_fp8x2_storage_t)v, __NV_E4M3);
    return __half22float2(*(__half2*)&hr);
}

__device__ __forceinline__ void ldmA(uint32_t addr, uint32_t& a0, uint32_t& a1,
                                     uint32_t& a2, uint32_t& a3) {
    asm volatile("ldmatrix.sync.aligned.m8n8.x4.shared.b16 {%0,%1,%2,%3},[%4];"
                 : "=r"(a0), "=r"(a1), "=r"(a2), "=r"(a3) : "r"(addr));
}
__device__ __forceinline__ void ldmBT(uint32_t addr, uint32_t& b0, uint32_t& b1,
                                      uint32_t& b2, uint32_t& b3) {
    asm volatile("ldmatrix.sync.aligned.m8n8.x4.trans.shared.b16 {%0,%1,%2,%3},[%4];"
                 : "=r"(b0), "=r"(b1), "=r"(b2), "=r"(b3) : "r"(addr));
}
__device__ __forceinline__ void mma16816(float* c, uint32_t a0, uint32_t a1,
                                         uint32_t a2, uint32_t a3,
                                         uint32_t b0, uint32_t b1) {
    asm volatile("mma.sync.aligned.m16n8k16.row.col.f32.bf16.bf16.f32 "
                 "{%0,%1,%2,%3},{%4,%5,%6,%7},{%8,%9},{%0,%1,%2,%3};"
                 : "+f"(c[0]), "+f"(c[1]), "+f"(c[2]), "+f"(c[3])
                 : "r"(a0), "r"(a1), "r"(a2), "r"(a3), "r"(b0), "r"(b1));
}

// K-chunked core: C[warp 16 rows x 64 cols] += A[16 x 16*KS] @ B[16*KS x 64]
// aStride/bStride in bf16 units; KS = number of K=16 steps.
template<int KS, int ASTR>
__device__ __forceinline__ void mma_core_t(uint32_t xtw, uint32_t wtb, int l,
                                           float cf[8][4]) {
    uint32_t arow = (uint32_t)(((l & 7) + ((l >> 3) & 1) * 8));
    uint32_t aAddr = xtw + (arow * ASTR + (uint32_t)(l >> 4) * 8) * 2;
    uint32_t bAddr = wtb + (arow * STRIDE + (uint32_t)(l >> 4) * 8) * 2;
    #pragma unroll
    for (int ks = 0; ks < KS; ks++) {
        uint32_t a0, a1, a2, a3;
        ldmA(aAddr + ks * 32, a0, a1, a2, a3);
        #pragma unroll
        for (int np = 0; np < 4; np++) {
            uint32_t b0, b1, b2, b3;
            ldmBT(bAddr + (uint32_t)(ks * 16 * STRIDE + np * 16) * 2, b0, b1, b2, b3);
            mma16816(cf[2 * np],     a0, a1, a2, a3, b0, b1);
            mma16816(cf[2 * np + 1], a0, a1, a2, a3, b2, b3);
        }
    }
}

// ---------------------------------------------------------------------------
// Adjacency build
// ---------------------------------------------------------------------------
__global__ void k_zero() {
    int n = blockIdx.x * blockDim.x + threadIdx.x;
    if (n < NN) g_cnt[n] = 0;
}
__global__ void k_build(const int* __restrict__ ei) {
    int e = blockIdx.x * blockDim.x + threadIdx.x;
    if (e < NE) {
        int u = ei[e];
        int p = ei[NE + e];
        int s1 = atomicAdd(&g_cnt[u], 1);
        if (s1 < CAP) g_adj[(size_t)u * CAP + s1] = p;   // message p -> u
        int s2 = atomicAdd(&g_cnt[p], 1);
        if (s2 < CAP) g_adj[(size_t)p * CAP + s2] = u;   // message u -> p
    }
}

// ---------------------------------------------------------------------------
// Feature projection: g_xb[n] = bf16(feat[n](128) @ W + b + emb[n])
// Single K-pass: full 128-col x tile + full 128x64 W tile, one sync.
// bid = blockIdx.x + bidOff; [0,GU) users, [GU,GU+GP) products.
// ---------------------------------------------------------------------------
__global__ __launch_bounds__(256, 3) void k_feat_t(
    const float* __restrict__ uf, const float* __restrict__ pf,
    const float* __restrict__ ue, const float* __restrict__ pe,
    const float* __restrict__ Wuf, const float* __restrict__ buf_,
    const float* __restrict__ Wpf, const float* __restrict__ bpf,
    int bidOff)
{
    __shared__ __align__(16) __nv_bfloat16 xt[128 * XSTR];   // 34.8 KB
    __shared__ __align__(16) __nv_bfloat16 wt[128 * STRIDE]; // 18.4 KB
    __shared__ float bs[64];

    int bid = blockIdx.x + bidOff;
    bool isUser = bid < GU;
    int lrow0 = isUser ? bid * 128 : (bid - GU) * 128;
    int nloc  = isUser ? NU : NP;
    const float* feat = isUser ? uf : pf;
    const float* emb  = isUser ? ue : pe;
    const float* W    = isUser ? Wuf : Wpf;
    const float* b    = isUser ? buf_ : bpf;
    int grow0 = isUser ? lrow0 : NU + lrow0;

    int tid = threadIdx.x;
    if (tid < 32) ((float2*)bs)[tid] = ((const float2*)b)[tid];

    const float4* W4 = (const float4*)W;
    const float4* f4 = (const float4*)feat;   // row stride 32 float4

    // W full (128x64 fp32 = 2048 f4), 8 per thread
    #pragma unroll
    for (int i = 0; i < 8; i++) {
        int idx = tid + i * 256, r = idx >> 4, c4 = idx & 15;
        float4 v = W4[idx];
        *(uint2*)(&wt[r * STRIDE + c4 * 4]) =
            make_uint2(pack_bf2(v.x, v.y), pack_bf2(v.z, v.w));
    }
    // x full (128 rows x 32 f4), 16 per thread
    #pragma unroll
    for (int i = 0; i < 16; i++) {
        int idx = tid + i * 256, r = idx >> 5, c4 = idx & 31;
        int lr = lrow0 + r;
        float4 v = make_float4(0.f, 0.f, 0.f, 0.f);
        if (lr < nloc) v = f4[(size_t)lr * 32 + c4];
        *(uint2*)(&xt[r * XSTR + c4 * 4]) =
            make_uint2(pack_bf2(v.x, v.y), pack_bf2(v.z, v.w));
    }
    __syncthreads();

    int l = tid & 31, w = tid >> 5;
    float cf[8][4];
    #pragma unroll
    for (int j = 0; j < 8; j++)
        #pragma unroll
        for (int q = 0; q < 4; q++) cf[j][q] = 0.f;

    mma_core_t<8, XSTR>(
        (uint32_t)__cvta_generic_to_shared(xt) + (uint32_t)(w * 16 * XSTR) * 2,
        (uint32_t)__cvta_generic_to_shared(wt), l, cf);

    int rl = w * 16 + (l >> 2);
    #pragma unroll
    for (int half = 0; half < 2; half++) {
        int lr = lrow0 + rl + half * 8;
        if (lr < nloc) {
            size_t gr = (size_t)(grow0 + rl + half * 8);
            #pragma unroll
            for (int j = 0; j < 8; j++) {
                int c2 = j * 4 + (l & 3);
                float2 ev = ((const float2*)emb)[(size_t)lr * 32 + c2];
                g_xb[gr * 32 + c2] = __floats2bfloat162_rn(
                    cf[j][half * 2 + 0] + bs[c2 * 2]     + ev.x,
                    cf[j][half * 2 + 1] + bs[c2 * 2 + 1] + ev.y);
            }
        }
    }
}

// ---------------------------------------------------------------------------
// k_mm: g_h8[n] = fp8( (g_xb[n] @ W) * (epiDis ? dis[n] : 1) )
// 256 rows/block (two 128-row tiles share one weight load).
// bid = blockIdx.x + bidOff; [0,GU2) users, [GU2,GU2+GP2) products.
// ---------------------------------------------------------------------------
__global__ __launch_bounds__(256) void k_mm(
    const float* __restrict__ Wu, const float* __restrict__ Wp, int epiDis,
    int bidOff)
{
    __shared__ __align__(16) __nv_bfloat16 xt[128 * STRIDE];
    __shared__ __align__(16) __nv_bfloat16 wt[64 * STRIDE];

    int bid = blockIdx.x + bidOff;
    bool isUser = bid < GU2;
    int lrow00 = isUser ? bid * 256 : (bid - GU2) * 256;
    int nloc  = isUser ? NU : NP;
    int gbase = isUser ? 0 : NU;
    const float* W = isUser ? Wu : Wp;

    int tid = threadIdx.x;
    #pragma unroll
    for (int i = 0; i < 4; i++) {
        int idx = tid + i * 256, r = idx >> 4, c4 = idx & 15;
        float4 v = ((const float4*)W)[idx];
        *(uint2*)(&wt[r * STRIDE + c4 * 4]) =
            make_uint2(pack_bf2(v.x, v.y), pack_bf2(v.z, v.w));
    }

    int l = tid & 31, w = tid >> 5;
    const uint4* x4 = (const uint4*)g_xb;

    #pragma unroll
    for (int t = 0; t < 2; t++) {
        int lrow0 = lrow00 + t * 128;
        __syncthreads();   // tile t input not yet needed by others / prev MMA done
        #pragma unroll
        for (int i = 0; i < 4; i++) {
            int idx = tid + i * 256, r = idx >> 3, c = idx & 7;
            int lr = lrow0 + r;
            uint4 v = make_uint4(0u, 0u, 0u, 0u);
            if (lr < nloc) v = x4[(size_t)(gbase + lr) * 8 + c];
            *(uint4*)(&xt[r * STRIDE + c * 8]) = v;
        }
        __syncthreads();

        float cf[8][4];
        #pragma unroll
        for (int j = 0; j < 8; j++)
            #pragma unroll
            for (int q = 0; q < 4; q++) cf[j][q] = 0.f;

        mma_core_t<4, STRIDE>(
            (uint32_t)__cvta_generic_to_shared(xt) + (uint32_t)(w * 16 * STRIDE) * 2,
            (uint32_t)__cvta_generic_to_shared(wt), l, cf);

        int rl = w * 16 + (l >> 2);
        #pragma unroll
        for (int half = 0; half < 2; half++) {
            int lr = lrow0 + rl + half * 8;
            if (lr < nloc) {
                int gr = gbase + lr;
                float d = epiDis ? rsqrtf((float)(g_cnt[gr] + 1)) : 1.f;
                #pragma unroll
                for (int j = 0; j < 8; j++) {
                    int c2 = j * 4 + (l & 3);
                    g_h8[(size_t)gr * 32 + c2] = f2_to_fp8x2(
                        cf[j][half * 2 + 0] * d, cf[j][half * 2 + 1] * d);
                }
            }
        }
    }
}

// ---------------------------------------------------------------------------
// k_agg: g_xb[n] = act( b + dis[n] * (g_h8[n] + sum_{src in adj[n]} g_h8[src]) )
// HALF-warp per node (fp8 rows are 64B = 16 lanes x 4B); node range split.
// ---------------------------------------------------------------------------
__global__ __launch_bounds__(256) void k_agg(const float* __restrict__ b,
                                             int doRelu, int nodeBase, int nNodes)
{
    int ln = blockIdx.x * 16 + (threadIdx.x >> 4);
    if (ln >= nNodes) return;
    int n = nodeBase + ln;
    int lane = threadIdx.x & 15;          // 4 fp8 cols pairs => cols [4l,4l+4)
    int c = g_cnt[n];
    if (c > CAP) c = CAP;
    float d = rsqrtf((float)(c + 1));
    const unsigned* h32 = (const unsigned*)g_h8;   // 4B = 4 fp8 values
    unsigned own = h32[(size_t)n * 16 + lane];
    float2 sA = fp8x2_to_f2((unsigned short)(own & 0xffffu));
    float2 sB = fp8x2_to_f2((unsigned short)(own >> 16));
    size_t base = (size_t)n * CAP;
    for (int i0 = 0; i0 < c; i0 += 16) {
        int m = min(16, c - i0);
        int srcl = (lane < m) ? g_adj[base + i0 + lane] : 0;
        int i = 0;
        for (; i + 3 < m; i += 4) {
            int s0 = __shfl_sync(0xffffffffu, srcl, i,     16);
            int s1 = __shfl_sync(0xffffffffu, srcl, i + 1, 16);
            int s2 = __shfl_sync(0xffffffffu, srcl, i + 2, 16);
            int s3 = __shfl_sync(0xffffffffu, srcl, i + 3, 16);
            unsigned r0 = h32[(size_t)s0 * 16 + lane];
            unsigned r1 = h32[(size_t)s1 * 16 + lane];
            unsigned r2 = h32[(size_t)s2 * 16 + lane];
            unsigned r3 = h32[(size_t)s3 * 16 + lane];
            float2 a0 = fp8x2_to_f2((unsigned short)(r0 & 0xffffu));
            float2 b0 = fp8x2_to_f2((unsigned short)(r0 >> 16));
            float2 a1 = fp8x2_to_f2((unsigned short)(r1 & 0xffffu));
            float2 b1 = fp8x2_to_f2((unsigned short)(r1 >> 16));
            float2 a2 = fp8x2_to_f2((unsigned short)(r2 & 0xffffu));
            float2 b2 = fp8x2_to_f2((unsigned short)(r2 >> 16));
            float2 a3 = fp8x2_to_f2((unsigned short)(r3 & 0xffffu));
            float2 b3 = fp8x2_to_f2((unsigned short)(r3 >> 16));
            sA.x += (a0.x + a1.x) + (a2.x + a3.x);
            sA.y += (a0.y + a1.y) + (a2.y + a3.y);
            sB.x += (b0.x + b1.x) + (b2.x + b3.x);
            sB.y += (b0.y + b1.y) + (b2.y + b3.y);
        }
        for (; i < m; i++) {
            int s0 = __shfl_sync(0xffffffffu, srcl, i, 16);
            unsigned r0 = h32[(size_t)s0 * 16 + lane];
            float2 a0 = fp8x2_to_f2((unsigned short)(r0 & 0xffffu));
            float2 b0 = fp8x2_to_f2((unsigned short)(r0 >> 16));
            sA.x += a0.x; sA.y += a0.y;
            sB.x += b0.x; sB.y += b0.y;
        }
    }
    float4 bv = ((const float4*)b)[lane];
    float v0 = bv.x + d * sA.x;
    float v1 = bv.y + d * sA.y;
    float v2 = bv.z + d * sB.x;
    float v3 = bv.w + d * sB.y;
    if (doRelu) {
        v0 = fmaxf(v0, 0.f); v1 = fmaxf(v1, 0.f);
        v2 = fmaxf(v2, 0.f); v3 = fmaxf(v3, 0.f);
    }
    ((uint2*)g_xb)[(size_t)n * 16 + lane] =
        make_uint2(pack_bf2(v0, v1), pack_bf2(v2, v3));
}

// ---------------------------------------------------------------------------
// k_prededge: h = relu(A[u]+B[p]+b1); out = 5*sigmoid(h.W2 + b2)
// 8 lanes per edge (4 edges/warp); uint2 row reads (8B/lane = 8 fp8 cols).
// ---------------------------------------------------------------------------
__global__ __launch_bounds__(256) void k_prededge(
    const int* __restrict__ ei,
    const float* __restrict__ b1, const float* __restrict__ W2,
    const float* __restrict__ b2, float* __restrict__ out)
{
    __shared__ float b1s[64], w2s[64];
    __shared__ float b2v;
    int tid = threadIdx.x;
    if (tid < 64) { b1s[tid] = b1[tid]; w2s[tid] = W2[tid]; }
    if (tid == 0) b2v = b2[0];
    __syncthreads();

    int e = blockIdx.x * 32 + (tid >> 3);
    if (e >= NE) return;
    int lg = tid & 7;            // 8 lanes/edge, 8 fp8 cols per lane
    int u = ei[e];
    int p = ei[NE + e];
    uint2 ar = ((const uint2*)g_h8)[(size_t)u * 8 + lg];
    uint2 br = ((const uint2*)g_h8)[(size_t)(NU + p) * 8 + lg];
    float4 b1a = ((const float4*)b1s)[lg * 2];
    float4 b1b = ((const float4*)b1s)[lg * 2 + 1];
    float4 w2a = ((const float4*)w2s)[lg * 2];
    float4 w2b = ((const float4*)w2s)[lg * 2 + 1];
    float2 a0 = fp8x2_to_f2((unsigned short)(ar.x & 0xffffu));
    float2 a1 = fp8x2_to_f2((unsigned short)(ar.x >> 16));
    float2 a2 = fp8x2_to_f2((unsigned short)(ar.y & 0xffffu));
    float2 a3 = fp8x2_to_f2((unsigned short)(ar.y >> 16));
    float2 c0 = fp8x2_to_f2((unsigned short)(br.x & 0xffffu));
    float2 c1 = fp8x2_to_f2((unsigned short)(br.x >> 16));
    float2 c2 = fp8x2_to_f2((unsigned short)(br.y & 0xffffu));
    float2 c3 = fp8x2_to_f2((unsigned short)(br.y >> 16));
    float h0 = fmaxf(a0.x + c0.x + b1a.x, 0.f);
    float h1 = fmaxf(a0.y + c0.y + b1a.y, 0.f);
    float h2 = fmaxf(a1.x + c1.x + b1a.z, 0.f);
    float h3 = fmaxf(a1.y + c1.y + b1a.w, 0.f);
    float h4 = fmaxf(a2.x + c2.x + b1b.x, 0.f);
    float h5 = fmaxf(a2.y + c2.y + b1b.y, 0.f);
    float h6 = fmaxf(a3.x + c3.x + b1b.z, 0.f);
    float h7 = fmaxf(a3.y + c3.y + b1b.w, 0.f);
    float part = (h0 * w2a.x + h1 * w2a.y + h2 * w2a.z + h3 * w2a.w)
               + (h4 * w2b.x + h5 * w2b.y + h6 * w2b.z + h7 * w2b.w);
    #pragma unroll
    for (int off = 4; off; off >>= 1)
        part += __shfl_xor_sync(0xffffffffu, part, off);
    if (lg == 0) {
        float z = part + b2v;
        out[e] = 5.f / (1.f + expf(-z));
    }
}

// ---------------------------------------------------------------------------
extern "C" void kernel_launch(void* const* d_in, const int* in_sizes, int n_in,
                              void* d_out, int out_size)
{
    const int*   ei  = (const int*)d_in[0];   // [2, NE] int32
    const float* uf  = (const float*)d_in[1];
    const float* pf  = (const float*)d_in[2];
    const float* ue  = (const float*)d_in[3];
    const float* pe  = (const float*)d_in[4];
    const float* Wuf = (const float*)d_in[5];
    const float* buf_= (const float*)d_in[6];
    const float* Wpf = (const float*)d_in[7];
    const float* bpf = (const float*)d_in[8];
    const float* c1W = (const float*)d_in[9];
    const float* c1b = (const float*)d_in[10];
    const float* c2W = (const float*)d_in[11];
    const float* c2b = (const float*)d_in[12];
    const float* pW1 = (const float*)d_in[13];
    const float* pb1 = (const float*)d_in[14];
    const float* pW2 = (const float*)d_in[15];
    const float* pb2 = (const float*)d_in[16];
    float* out = (float*)d_out;

    const int AGU = NU / 16;   // agg blocks users
    const int AGP = NP / 16;   // agg blocks products

    // Two-stream pipeline. Streams/events are created per call and leaked
    // intentionally (destroying objects used in an active capture invalidates
    // it; a handful of host objects per harness call is benign).
    cudaStream_t s2 = 0;
    cudaEvent_t ev[8] = {};
    bool par = (cudaStreamCreateWithFlags(&s2, cudaStreamNonBlocking) == cudaSuccess);
    for (int i = 0; par && i < 8; i++)
        par = (cudaEventCreateWithFlags(&ev[i], cudaEventDisableTiming) == cudaSuccess);

    if (par) {
        // fork
        cudaEventRecord(ev[0], 0);
        cudaStreamWaitEvent(s2, ev[0], 0);

        // B: adjacency; A: user features (independent)
        k_zero <<<(NN + 255) / 256, 256, 0, s2>>>();
        k_build<<<(NE + 255) / 256, 256, 0, s2>>>(ei);
        cudaEventRecord(ev[1], s2);                         // build done
        k_feat_t<<<GU, 256>>>(uf, pf, ue, pe, Wuf, buf_, Wpf, bpf, 0);
        k_feat_t<<<GP, 256, 0, s2>>>(uf, pf, ue, pe, Wuf, buf_, Wpf, bpf, GU);

        // mm1 halves (users on A needs build's g_cnt)
        cudaStreamWaitEvent(0, ev[1], 0);
        k_mm<<<GU2, 256>>>(c1W, c1W, 1, 0);
        cudaEventRecord(ev[2], 0);                          // mm1_u done
        k_mm<<<GP2, 256, 0, s2>>>(c1W, c1W, 1, GU2);
        cudaEventRecord(ev[3], s2);                         // mm1_p done

        // agg1 halves (each needs BOTH mm1 halves) -> mm2 halves (own half only)
        cudaStreamWaitEvent(0, ev[3], 0);
        k_agg<<<AGU, 256>>>(c1b, 1, 0, NU);
        k_mm <<<GU2, 256>>>(c2W, c2W, 1, 0);
        cudaEventRecord(ev[4], 0);                          // mm2_u done
        cudaStreamWaitEvent(s2, ev[2], 0);
        k_agg<<<AGP, 256, 0, s2>>>(c1b, 1, NU, NP);
        k_mm <<<GP2, 256, 0, s2>>>(c2W, c2W, 1, GU2);
        cudaEventRecord(ev[5], s2);                         // mm2_p done

        // agg2 halves -> mm3 (prednode) halves
        cudaStreamWaitEvent(0, ev[5], 0);
        k_agg<<<AGU, 256>>>(c2b, 0, 0, NU);
        k_mm <<<GU2, 256>>>(pW1, pW1 + 4096, 0, 0);
        cudaStreamWaitEvent(s2, ev[4], 0);
        k_agg<<<AGP, 256, 0, s2>>>(c2b, 0, NU, NP);
        k_mm <<<GP2, 256, 0, s2>>>(pW1, pW1 + 4096, 0, GU2);
        cudaEventRecord(ev[6], s2);                         // mm3_p done (B's last)

        // prededge needs both mm3 halves
        cudaStreamWaitEvent(0, ev[6], 0);
        k_prededge<<<NE / 32, 256>>>(ei, pb1, pW2, pb2, out);
    } else {
        k_zero <<<(NN + 255) / 256, 256>>>();
        k_build<<<(NE + 255) / 256, 256>>>(ei);
        k_feat_t<<<GU + GP, 256>>>(uf, pf, ue, pe, Wuf, buf_, Wpf, bpf, 0);
        k_mm <<<GU2 + GP2, 256>>>(c1W, c1W, 1, 0);
        k_agg<<<NN / 16, 256>>>(c1b, 1, 0, NN);
        k_mm <<<GU2 + GP2, 256>>>(c2W, c2W, 1, 0);
        k_agg<<<NN / 16, 256>>>(c2b, 0, 0, NN);
        k_mm <<<GU2 + GP2, 256>>>(pW1, pW1 + 4096, 0, 0);
        k_prededge<<<NE / 32, 256>>>(ei, pb1, pW2, pb2, out);
    }
}